// round 2
// baseline (speedup 1.0000x reference)
#include <cuda_runtime.h>
#include <cuda_bf16.h>
#include <math.h>

// ---------------- problem constants ----------------
#define S      15
#define BATCH  32
#define NNODE  5000
#define NEDGE  80000
#define NEDGE_SL (NEDGE + NNODE)   // with self loops = 85000
#define FIN    16
#define HID    512
#define G3     1536                // 3*HID
#define SB     (S*BATCH)           // 480
#define K5     5000

// ---------------- device scratch (no allocs allowed) ----------------
struct __align__(8) Edge { int s; float w; };

__device__ int   g_indeg[NNODE];
__device__ int   g_off[NNODE + 1];
__device__ int   g_pos[NNODE];
__device__ float g_dinv[NNODE];
__device__ Edge  g_edges[NEDGE_SL];
__device__ int   g_is64;

__device__ float g_g[SB * NNODE];       // GCN output, [480][5000]
__device__ float g_gi0[SB * G3];        // precomputed layer-0 input gates
__device__ float g_gi1[2][BATCH * G3];  // double-buffered layer-1 input gates
__device__ float g_out1[S * BATCH * HID];
__device__ float g_h0[2][BATCH * HID];
__device__ float g_h1[2][BATCH * HID];

// ---------------- packed f32x2 helpers ----------------
#define FFMA2(c, a, b) asm("fma.rn.f32x2 %0, %1, %2, %0;" : "+l"(c) : "l"(a), "l"(b))

__device__ __forceinline__ float hsum2(unsigned long long v) {
    float lo, hi;
    asm("mov.b64 {%0,%1}, %2;" : "=f"(lo), "=f"(hi) : "l"(v));
    return lo + hi;
}

// ---------------- prep kernels ----------------
__global__ void init_kernel(const int* __restrict__ ei) {
    int i = blockIdx.x * blockDim.x + threadIdx.x;
    if (i < NNODE) g_indeg[i] = 1;                 // self loop
    if (i < BATCH * HID) { g_h0[0][i] = 0.f; g_h1[0][i] = 0.f; }
    if (i == 0) {
        // detect whether edge_index is int64 (high words all zero) or int32
        int f = 1;
        for (int q = 0; q < 64; q++) if (ei[2 * q + 1] != 0) { f = 0; break; }
        g_is64 = f;
    }
}

__global__ void count_kernel(const int* __restrict__ ei) {
    int e = blockIdx.x * blockDim.x + threadIdx.x;
    if (e >= NEDGE) return;
    int is64 = g_is64;
    int t = is64 ? ei[2 * (NEDGE + e)] : ei[NEDGE + e];
    atomicAdd(&g_indeg[t], 1);
}

__global__ void scan_kernel() {
    __shared__ int ssum[1024];
    int t = threadIdx.x;
    int vals[5];
    int s = 0;
    #pragma unroll
    for (int q = 0; q < 5; q++) {
        int idx = t * 5 + q;
        vals[q] = (idx < NNODE) ? g_indeg[idx] : 0;
        s += vals[q];
    }
    ssum[t] = s;
    __syncthreads();
    for (int off = 1; off < 1024; off <<= 1) {
        int v = (t >= off) ? ssum[t - off] : 0;
        __syncthreads();
        ssum[t] += v;
        __syncthreads();
    }
    int run = ssum[t] - s;  // exclusive prefix
    #pragma unroll
    for (int q = 0; q < 5; q++) {
        int idx = t * 5 + q;
        if (idx < NNODE) {
            g_off[idx] = run;
            g_pos[idx] = run;
            g_dinv[idx] = rsqrtf((float)vals[q]);
            run += vals[q];
        }
    }
    if (t == 1023) g_off[NNODE] = ssum[1023];
}

__global__ void fill_kernel(const int* __restrict__ ei) {
    int e = blockIdx.x * blockDim.x + threadIdx.x;
    if (e >= NEDGE_SL) return;
    int is64 = g_is64;
    int s, t;
    if (e < NEDGE) {
        s = is64 ? ei[2 * e] : ei[e];
        t = is64 ? ei[2 * (NEDGE + e)] : ei[NEDGE + e];
    } else {
        s = t = e - NEDGE;
    }
    int idx = atomicAdd(&g_pos[t], 1);
    Edge E; E.s = s; E.w = g_dinv[s] * g_dinv[t];
    g_edges[idx] = E;
}

// ---------------- fused GCN (one CTA per (s,b) slice) ----------------
// smem: hA[10000], hB[10000]  = 80000 bytes
__global__ void gcn_kernel(const float* __restrict__ x, const float* __restrict__ W1,
                           const float* __restrict__ b1, const float* __restrict__ W2,
                           const float* __restrict__ b2) {
    extern __shared__ float sm[];
    float* hA = sm;
    float* hB = sm + 2 * NNODE;
    int sb = blockIdx.x;
    int s = sb >> 5;
    int tid = threadIdx.x;

    float w10[FIN], w11[FIN];
    #pragma unroll
    for (int f = 0; f < FIN; f++) {
        w10[f] = W1[s * (FIN * 2) + f * 2 + 0];
        w11[f] = W1[s * (FIN * 2) + f * 2 + 1];
    }
    float b10 = b1[s * 2 + 0], b11 = b1[s * 2 + 1];
    float w20 = W2[s * 2 + 0], w21 = W2[s * 2 + 1];
    float b2s = b2[s];

    const float* xb = x + (size_t)sb * NNODE * FIN;
    // linear: h = x @ W1  -> hA[n][0..1]
    for (int n = tid; n < NNODE; n += 512) {
        const float4* xp = (const float4*)(xb + (size_t)n * FIN);
        float xv[16];
        *(float4*)&xv[0]  = xp[0];
        *(float4*)&xv[4]  = xp[1];
        *(float4*)&xv[8]  = xp[2];
        *(float4*)&xv[12] = xp[3];
        float a0 = 0.f, a1 = 0.f;
        #pragma unroll
        for (int f = 0; f < FIN; f++) { a0 += xv[f] * w10[f]; a1 += xv[f] * w11[f]; }
        hA[2 * n] = a0; hA[2 * n + 1] = a1;
    }
    __syncthreads();
    // propagate 1 + bias + relu -> hB
    for (int n = tid; n < NNODE; n += 512) {
        int e0 = g_off[n], e1 = g_off[n + 1];
        float a0 = 0.f, a1 = 0.f;
        for (int e = e0; e < e1; e++) {
            Edge E = g_edges[e];
            a0 += E.w * hA[2 * E.s];
            a1 += E.w * hA[2 * E.s + 1];
        }
        hB[2 * n]     = fmaxf(a0 + b10, 0.f);
        hB[2 * n + 1] = fmaxf(a1 + b11, 0.f);
    }
    __syncthreads();
    // linear 2 -> hA[n]
    for (int n = tid; n < NNODE; n += 512)
        hA[n] = hB[2 * n] * w20 + hB[2 * n + 1] * w21;
    __syncthreads();
    // propagate 2 + bias + tanh -> g_g
    float* gout = g_g + (size_t)sb * NNODE;
    for (int n = tid; n < NNODE; n += 512) {
        int e0 = g_off[n], e1 = g_off[n + 1];
        float q = 0.f;
        for (int e = e0; e < e1; e++) {
            Edge E = g_edges[e];
            q += E.w * hA[E.s];
        }
        gout[n] = tanhf(q + b2s);
    }
}

// ---------------- gi0 = g @ w_ih0^T + b_ih0  (fp32x2 tiled GEMM) ----------------
#define BM 48
#define BN 96
#define KC 16
#define NCH ((K5 + KC - 1) / KC)   // 313

__global__ __launch_bounds__(256) void gemm_gi0_kernel(const float* __restrict__ wih0,
                                                       const float* __restrict__ bih0) {
    __shared__ __align__(16) float a_sm[BM * 18];
    __shared__ __align__(16) float b_sm[BN * 18];
    int tid = threadIdx.x;
    int m0 = blockIdx.x * BM;
    int n0 = blockIdx.y * BN;
    int tx = tid & 15, ty = tid >> 4;

    unsigned long long acc[3][6];
    #pragma unroll
    for (int i = 0; i < 3; i++)
        #pragma unroll
        for (int j = 0; j < 6; j++) acc[i][j] = 0ull;

    int ra[3], ka[3], rb[6], kb[6];
    #pragma unroll
    for (int i = 0; i < 3; i++) { int e = tid + i * 256; ra[i] = e >> 4; ka[i] = e & 15; }
    #pragma unroll
    for (int i = 0; i < 6; i++) { int e = tid + i * 256; rb[i] = e >> 4; kb[i] = e & 15; }

    float pa[3], pb[6];
    // prefetch chunk 0
    #pragma unroll
    for (int i = 0; i < 3; i++) pa[i] = g_g[(size_t)(m0 + ra[i]) * K5 + ka[i]];
    #pragma unroll
    for (int i = 0; i < 6; i++) pb[i] = wih0[(size_t)(n0 + rb[i]) * K5 + kb[i]];

    for (int c = 0; c < NCH; c++) {
        #pragma unroll
        for (int i = 0; i < 3; i++) a_sm[ra[i] * 18 + ka[i]] = pa[i];
        #pragma unroll
        for (int i = 0; i < 6; i++) b_sm[rb[i] * 18 + kb[i]] = pb[i];
        __syncthreads();
        int k0n = (c + 1) * KC;
        if (c + 1 < NCH) {
            #pragma unroll
            for (int i = 0; i < 3; i++) {
                int kg = k0n + ka[i];
                pa[i] = (kg < K5) ? g_g[(size_t)(m0 + ra[i]) * K5 + kg] : 0.f;
            }
            #pragma unroll
            for (int i = 0; i < 6; i++) {
                int kg = k0n + kb[i];
                pb[i] = (kg < K5) ? wih0[(size_t)(n0 + rb[i]) * K5 + kg] : 0.f;
            }
        }
        #pragma unroll
        for (int kk = 0; kk < KC; kk += 2) {
            unsigned long long av[3], bv[6];
            #pragma unroll
            for (int i = 0; i < 3; i++)
                av[i] = *(const unsigned long long*)&a_sm[(ty * 3 + i) * 18 + kk];
            #pragma unroll
            for (int j = 0; j < 6; j++)
                bv[j] = *(const unsigned long long*)&b_sm[(tx * 6 + j) * 18 + kk];
            #pragma unroll
            for (int i = 0; i < 3; i++)
                #pragma unroll
                for (int j = 0; j < 6; j++)
                    FFMA2(acc[i][j], av[i], bv[j]);
        }
        __syncthreads();
    }
    #pragma unroll
    for (int i = 0; i < 3; i++)
        #pragma unroll
        for (int j = 0; j < 6; j++) {
            int m = m0 + ty * 3 + i;
            int n = n0 + tx * 6 + j;
            g_gi0[(size_t)m * G3 + n] = hsum2(acc[i][j]) + bih0[n];
        }
}

// ---------------- GRU step pieces ----------------
// smem layout (floats): s_h[32*514] then s_w (up to 32*512)
#define HPAD 514

__device__ void gru_update(const float* __restrict__ gi,   // [B][1536] (bias included)
                           const float* __restrict__ hin,  // [B][512]
                           float* __restrict__ hout,       // [B][512]
                           float* __restrict__ outcopy,    // [B][512]
                           const float* __restrict__ whh,  // [1536][512]
                           const float* __restrict__ bhh,  // [1536]
                           int jtile, float* sm) {
    float* s_h = sm;                 // [32][514]
    float* s_w = sm + BATCH * HPAD;  // [24][512]
    int tid = threadIdx.x;
    for (int e = tid; e < BATCH * HID; e += 256) {
        int b = e >> 9, kk = e & 511;
        s_h[b * HPAD + kk] = hin[e];
    }
    for (int e = tid; e < 3 * 8 * HID; e += 256) {
        int r = e >> 9, kk = e & 511;
        int g = r >> 3, jl = r & 7;
        s_w[r * HID + kk] = whh[((size_t)(g * HID + jtile * 8 + jl)) * HID + kk];
    }
    __syncthreads();
    int b = tid & 31, jl = tid >> 5;
    const unsigned long long* hp = (const unsigned long long*)(s_h + b * HPAD);
    const unsigned long long* wr = (const unsigned long long*)(s_w + (0 * 8 + jl) * HID);
    const unsigned long long* wz = (const unsigned long long*)(s_w + (1 * 8 + jl) * HID);
    const unsigned long long* wn = (const unsigned long long*)(s_w + (2 * 8 + jl) * HID);
    unsigned long long ar = 0ull, az = 0ull, an = 0ull;
    #pragma unroll 8
    for (int q = 0; q < HID / 2; q++) {
        unsigned long long h2 = hp[q];
        FFMA2(ar, h2, wr[q]);
        FFMA2(az, h2, wz[q]);
        FFMA2(an, h2, wn[q]);
    }
    int j = jtile * 8 + jl;
    float ghr = hsum2(ar) + bhh[j];
    float ghz = hsum2(az) + bhh[HID + j];
    float ghn = hsum2(an) + bhh[2 * HID + j];
    float gir = gi[b * G3 + j];
    float giz = gi[b * G3 + HID + j];
    float gin = gi[b * G3 + 2 * HID + j];
    float r = 1.f / (1.f + expf(-(gir + ghr)));
    float z = 1.f / (1.f + expf(-(giz + ghz)));
    float n = tanhf(gin + r * ghn);
    float hprev = s_h[b * HPAD + j];
    float hnew = (1.f - z) * n + z * hprev;
    hout[b * HID + j] = hnew;
    outcopy[b * HID + j] = hnew;
}

__device__ void gemm_gi1(const float* __restrict__ inp,  // out1[t] [32][512]
                         const float* __restrict__ wih,  // [1536][512]
                         const float* __restrict__ bih,  // [1536]
                         float* __restrict__ gi1,        // [32][1536]
                         int ctile, float* sm) {
    float* s_in = sm;
    float* s_w = sm + BATCH * HPAD;   // [32][512]
    int tid = threadIdx.x;
    for (int e = tid; e < BATCH * HID; e += 256) {
        int b = e >> 9, kk = e & 511;
        s_in[b * HPAD + kk] = inp[e];
    }
    for (int e = tid; e < 32 * HID; e += 256) {
        int r = e >> 9, kk = e & 511;
        s_w[e] = wih[((size_t)(ctile * 32 + r)) * HID + kk];
    }
    __syncthreads();
    int b = tid & 31, cg = tid >> 5;  // cg 0..7, 4 cols each
    const unsigned long long* ip = (const unsigned long long*)(s_in + b * HPAD);
    unsigned long long acc0 = 0ull, acc1 = 0ull, acc2 = 0ull, acc3 = 0ull;
    const unsigned long long* w0 = (const unsigned long long*)(s_w + (cg * 4 + 0) * HID);
    const unsigned long long* w1 = (const unsigned long long*)(s_w + (cg * 4 + 1) * HID);
    const unsigned long long* w2 = (const unsigned long long*)(s_w + (cg * 4 + 2) * HID);
    const unsigned long long* w3 = (const unsigned long long*)(s_w + (cg * 4 + 3) * HID);
    #pragma unroll 8
    for (int q = 0; q < HID / 2; q++) {
        unsigned long long h2 = ip[q];
        FFMA2(acc0, h2, w0[q]);
        FFMA2(acc1, h2, w1[q]);
        FFMA2(acc2, h2, w2[q]);
        FFMA2(acc3, h2, w3[q]);
    }
    int col = ctile * 32 + cg * 4;
    gi1[b * G3 + col + 0] = hsum2(acc0) + bih[col + 0];
    gi1[b * G3 + col + 1] = hsum2(acc1) + bih[col + 1];
    gi1[b * G3 + col + 2] = hsum2(acc2) + bih[col + 2];
    gi1[b * G3 + col + 3] = hsum2(acc3) + bih[col + 3];
}

// pipelined step kernel: k in [0, S+1]
//   CTAs [0,64):    layer0 step k        (valid k < S)
//   CTAs [64,128):  layer1 step k-2      (valid 0 <= k-2 < S)
//   CTAs [128,176): gi1 GEMM for step k-1 (valid 0 <= k-1 < S)
__global__ __launch_bounds__(256) void gru_step_kernel(
        int k,
        const float* __restrict__ w_hh0, const float* __restrict__ b_hh0,
        const float* __restrict__ w_ih1, const float* __restrict__ b_ih1,
        const float* __restrict__ w_hh1, const float* __restrict__ b_hh1,
        float* __restrict__ d_out) {
    extern __shared__ float sm[];
    int cta = blockIdx.x;
    if (cta < 64) {
        if (k >= S) return;
        gru_update(g_gi0 + (size_t)k * BATCH * G3, g_h0[k & 1], g_h0[(k + 1) & 1],
                   g_out1 + (size_t)k * BATCH * HID, w_hh0, b_hh0, cta, sm);
    } else if (cta < 128) {
        int t = k - 2;
        if (t < 0 || t >= S) return;
        gru_update(g_gi1[t & 1], g_h1[t & 1], g_h1[(t + 1) & 1],
                   d_out + (size_t)t * BATCH * HID, w_hh1, b_hh1, cta - 64, sm);
    } else {
        int t = k - 1;
        if (t < 0 || t >= S) return;
        gemm_gi1(g_out1 + (size_t)t * BATCH * HID, w_ih1, b_ih1, g_gi1[t & 1],
                 cta - 128, sm);
    }
}

__global__ void copy_hn_kernel(float* __restrict__ d_out) {
    int i = blockIdx.x * blockDim.x + threadIdx.x;
    if (i < BATCH * HID) {
        // final states live in buffer parity ((S-1)+1)&1 = 1
        d_out[S * BATCH * HID + i] = g_h0[1][i];
        d_out[S * BATCH * HID + BATCH * HID + i] = g_h1[1][i];
    }
}

// ---------------- host launch ----------------
extern "C" void kernel_launch(void* const* d_in, const int* in_sizes, int n_in,
                              void* d_out, int out_size) {
    const float* x     = (const float*)d_in[0];
    const int*   ei    = (const int*)d_in[1];   // int32 or int64, detected on device
    const float* W1    = (const float*)d_in[2];
    const float* b1    = (const float*)d_in[3];
    const float* W2    = (const float*)d_in[4];
    const float* b2    = (const float*)d_in[5];
    const float* w_ih0 = (const float*)d_in[6];
    const float* w_hh0 = (const float*)d_in[7];
    const float* b_ih0 = (const float*)d_in[8];
    const float* b_hh0 = (const float*)d_in[9];
    const float* w_ih1 = (const float*)d_in[10];
    const float* w_hh1 = (const float*)d_in[11];
    const float* b_ih1 = (const float*)d_in[12];
    const float* b_hh1 = (const float*)d_in[13];
    float* out = (float*)d_out;

    const int SMEM_GCN  = 2 * 2 * NNODE * (int)sizeof(float);              // 80000
    const int SMEM_STEP = (BATCH * HPAD + 32 * HID) * (int)sizeof(float);  // 131328

    cudaFuncSetAttribute(gcn_kernel, cudaFuncAttributeMaxDynamicSharedMemorySize, SMEM_GCN);
    cudaFuncSetAttribute(gru_step_kernel, cudaFuncAttributeMaxDynamicSharedMemorySize, SMEM_STEP);

    init_kernel<<<(BATCH * HID + 255) / 256, 256>>>(ei);
    count_kernel<<<(NEDGE + 255) / 256, 256>>>(ei);
    scan_kernel<<<1, 1024>>>();
    fill_kernel<<<(NEDGE_SL + 255) / 256, 256>>>(ei);

    gcn_kernel<<<SB, 512, SMEM_GCN>>>(x, W1, b1, W2, b2);
    gemm_gi0_kernel<<<dim3(SB / BM, G3 / BN), 256>>>(w_ih0, b_ih0);

    for (int k = 0; k < S + 2; k++)
        gru_step_kernel<<<176, 256, SMEM_STEP>>>(k, w_hh0, b_hh0, w_ih1, b_ih1,
                                                 w_hh1, b_hh1, out);

    copy_hn_kernel<<<(BATCH * HID + 255) / 256, 256>>>(out);
}

// round 3
// speedup vs baseline: 1.3199x; 1.3199x over previous
#include <cuda_runtime.h>
#include <cuda_bf16.h>
#include <math.h>

#define S      15
#define BATCH  32
#define NNODE  5000
#define NEDGE  80000
#define NEDGE_SL (NEDGE + NNODE)
#define FIN    16
#define HID    512
#define G3     1536
#define SB     (S*BATCH)
#define K5     5000
#define K5P    5024
#define MP     512
#define KCH    157

struct __align__(8) Edge { int s; float w; };

__device__ int   g_indeg[NNODE];
__device__ int   g_off[NNODE + 1];
__device__ int   g_pos[NNODE];
__device__ float g_dinv[NNODE];
__device__ Edge  g_edges[NEDGE_SL];
__device__ int   g_is64;

// bf16 hi/lo operands for gi0 GEMM (pads stay zero: never written)
__device__ __nv_bfloat16 g_ghi[MP * K5P];
__device__ __nv_bfloat16 g_glo[MP * K5P];
__device__ __nv_bfloat16 g_whi[G3 * K5P];
__device__ __nv_bfloat16 g_wlo[G3 * K5P];

__device__ float g_gi0[SB * G3];
__device__ float g_gi1[2][BATCH * G3];
__device__ float g_out1[S * BATCH * HID];
__device__ float g_h0[2][BATCH * HID];
__device__ float g_h1[2][BATCH * HID];

#define FFMA2(c, a, b) asm("fma.rn.f32x2 %0, %1, %2, %0;" : "+l"(c) : "l"(a), "l"(b))
__device__ __forceinline__ float hsum2(unsigned long long v) {
    float lo, hi;
    asm("mov.b64 {%0,%1}, %2;" : "=f"(lo), "=f"(hi) : "l"(v));
    return lo + hi;
}
__device__ __forceinline__ unsigned smem_u32(const void* p) {
    return (unsigned)__cvta_generic_to_shared(p);
}
__device__ __forceinline__ void ldm_x4(unsigned a, unsigned& r0, unsigned& r1,
                                       unsigned& r2, unsigned& r3) {
    asm volatile("ldmatrix.sync.aligned.m8n8.x4.shared.b16 {%0,%1,%2,%3}, [%4];"
                 : "=r"(r0), "=r"(r1), "=r"(r2), "=r"(r3) : "r"(a));
}
__device__ __forceinline__ void mma_bf16(float* d, const unsigned* a, const unsigned* b) {
    asm volatile(
        "mma.sync.aligned.m16n8k16.row.col.f32.bf16.bf16.f32 "
        "{%0,%1,%2,%3}, {%4,%5,%6,%7}, {%8,%9}, {%0,%1,%2,%3};"
        : "+f"(d[0]), "+f"(d[1]), "+f"(d[2]), "+f"(d[3])
        : "r"(a[0]), "r"(a[1]), "r"(a[2]), "r"(a[3]), "r"(b[0]), "r"(b[1]));
}

// ---------------- prep ----------------
__global__ void init_kernel(const int* __restrict__ ei) {
    int i = blockIdx.x * blockDim.x + threadIdx.x;
    if (i < NNODE) g_indeg[i] = 1;
    if (i < BATCH * HID) { g_h0[0][i] = 0.f; g_h1[0][i] = 0.f; }
    if (i == 0) {
        int f = 1;
        for (int q = 0; q < 64; q++) if (ei[2 * q + 1] != 0) { f = 0; break; }
        g_is64 = f;
    }
}
__global__ void count_kernel(const int* __restrict__ ei) {
    int e = blockIdx.x * blockDim.x + threadIdx.x;
    if (e >= NEDGE) return;
    int t = g_is64 ? ei[2 * (NEDGE + e)] : ei[NEDGE + e];
    atomicAdd(&g_indeg[t], 1);
}
__global__ void scan_kernel() {
    __shared__ int ssum[1024];
    int t = threadIdx.x;
    int vals[5]; int s = 0;
    #pragma unroll
    for (int q = 0; q < 5; q++) {
        int idx = t * 5 + q;
        vals[q] = (idx < NNODE) ? g_indeg[idx] : 0;
        s += vals[q];
    }
    ssum[t] = s;
    __syncthreads();
    for (int off = 1; off < 1024; off <<= 1) {
        int v = (t >= off) ? ssum[t - off] : 0;
        __syncthreads();
        ssum[t] += v;
        __syncthreads();
    }
    int run = ssum[t] - s;
    #pragma unroll
    for (int q = 0; q < 5; q++) {
        int idx = t * 5 + q;
        if (idx < NNODE) {
            g_off[idx] = run; g_pos[idx] = run;
            g_dinv[idx] = rsqrtf((float)vals[q]);
            run += vals[q];
        }
    }
    if (t == 1023) g_off[NNODE] = ssum[1023];
}
__global__ void fill_kernel(const int* __restrict__ ei) {
    int e = blockIdx.x * blockDim.x + threadIdx.x;
    if (e >= NEDGE_SL) return;
    int is64 = g_is64;
    int s, t;
    if (e < NEDGE) {
        s = is64 ? ei[2 * e] : ei[e];
        t = is64 ? ei[2 * (NEDGE + e)] : ei[NEDGE + e];
    } else { s = t = e - NEDGE; }
    int idx = atomicAdd(&g_pos[t], 1);
    Edge E; E.s = s; E.w = g_dinv[s] * g_dinv[t];
    g_edges[idx] = E;
}
__global__ void wconv_kernel(const float* __restrict__ wih0) {
    int i = blockIdx.x * blockDim.x + threadIdx.x;
    if (i >= G3 * K5) return;
    int n = i / K5, k = i - n * K5;
    float v = wih0[i];
    __nv_bfloat16 hi = __float2bfloat16(v);
    g_whi[(size_t)n * K5P + k] = hi;
    g_wlo[(size_t)n * K5P + k] = __float2bfloat16(v - __bfloat162float(hi));
}

// ---------------- fused GCN ----------------
__global__ void gcn_kernel(const float* __restrict__ x, const float* __restrict__ W1,
                           const float* __restrict__ b1, const float* __restrict__ W2,
                           const float* __restrict__ b2) {
    extern __shared__ float sm[];
    float* hA = sm;
    float* hB = sm + 2 * NNODE;
    int sb = blockIdx.x;
    int s = sb >> 5;
    int tid = threadIdx.x;

    float w10[FIN], w11[FIN];
    #pragma unroll
    for (int f = 0; f < FIN; f++) {
        w10[f] = W1[s * (FIN * 2) + f * 2 + 0];
        w11[f] = W1[s * (FIN * 2) + f * 2 + 1];
    }
    float b10 = b1[s * 2 + 0], b11 = b1[s * 2 + 1];
    float w20 = W2[s * 2 + 0], w21 = W2[s * 2 + 1];
    float b2s = b2[s];

    const float* xb = x + (size_t)sb * NNODE * FIN;
    for (int n = tid; n < NNODE; n += 512) {
        const float4* xp = (const float4*)(xb + (size_t)n * FIN);
        float xv[16];
        *(float4*)&xv[0] = xp[0]; *(float4*)&xv[4] = xp[1];
        *(float4*)&xv[8] = xp[2]; *(float4*)&xv[12] = xp[3];
        float a0 = 0.f, a1 = 0.f;
        #pragma unroll
        for (int f = 0; f < FIN; f++) { a0 += xv[f] * w10[f]; a1 += xv[f] * w11[f]; }
        hA[2 * n] = a0; hA[2 * n + 1] = a1;
    }
    __syncthreads();
    for (int n = tid; n < NNODE; n += 512) {
        int e0 = g_off[n], e1 = g_off[n + 1];
        float a0 = 0.f, a1 = 0.f;
        for (int e = e0; e < e1; e++) {
            Edge E = g_edges[e];
            a0 += E.w * hA[2 * E.s];
            a1 += E.w * hA[2 * E.s + 1];
        }
        hB[2 * n]     = fmaxf(a0 + b10, 0.f);
        hB[2 * n + 1] = fmaxf(a1 + b11, 0.f);
    }
    __syncthreads();
    for (int n = tid; n < NNODE; n += 512)
        hA[n] = hB[2 * n] * w20 + hB[2 * n + 1] * w21;
    __syncthreads();
    for (int n = tid; n < NNODE; n += 512) {
        int e0 = g_off[n], e1 = g_off[n + 1];
        float q = 0.f;
        for (int e = e0; e < e1; e++) {
            Edge E = g_edges[e];
            q += E.w * hA[E.s];
        }
        float g = tanhf(q + b2s);
        __nv_bfloat16 hi = __float2bfloat16(g);
        g_ghi[(size_t)sb * K5P + n] = hi;
        g_glo[(size_t)sb * K5P + n] = __float2bfloat16(g - __bfloat162float(hi));
    }
}

// ---------------- gi0 GEMM: bf16 split mma ----------------
#define GSTR 72                                   // smem row stride (bf16 elems)
#define SA_BYTES (2 * 2 * 64 * GSTR * 2)          // 36864
#define SB_BYTES (2 * 2 * 128 * GSTR * 2)         // 73728

__global__ __launch_bounds__(256) void gemm_gi0_kernel(const float* __restrict__ bih0) {
    extern __shared__ char smraw[];
    __nv_bfloat16* sA = (__nv_bfloat16*)smraw;                // [buf][hl][64][72]
    __nv_bfloat16* sB = (__nv_bfloat16*)(smraw + SA_BYTES);   // [buf][hl][128][72]
    unsigned sA_u = smem_u32(sA), sB_u = smem_u32(sB);

    int tid = threadIdx.x;
    int lane = tid & 31, warp = tid >> 5;
    int wm = warp >> 2, wn = warp & 3;
    int m0 = blockIdx.x * 64, n0 = blockIdx.y * 128;

    float d[2][4][4];
    #pragma unroll
    for (int i = 0; i < 2; i++)
        #pragma unroll
        for (int j = 0; j < 4; j++)
            #pragma unroll
            for (int q = 0; q < 4; q++) d[i][j][q] = 0.f;

    int a_hl[2], a_row[2], a_seg[2];
    #pragma unroll
    for (int i = 0; i < 2; i++) {
        int idx = tid + i * 256;
        a_hl[i] = idx >> 8; int r = idx & 255;
        a_row[i] = r >> 2; a_seg[i] = r & 3;
    }
    int b_hl[4], b_row[4], b_seg[4];
    #pragma unroll
    for (int i = 0; i < 4; i++) {
        int idx = tid + i * 256;
        b_hl[i] = idx >> 9; int r = idx & 511;
        b_row[i] = r >> 2; b_seg[i] = r & 3;
    }

    uint4 rA[2], rB[4];
    #pragma unroll
    for (int i = 0; i < 2; i++) {
        const __nv_bfloat16* src = a_hl[i] ? g_glo : g_ghi;
        rA[i] = *(const uint4*)(src + (size_t)(m0 + a_row[i]) * K5P + a_seg[i] * 8);
    }
    #pragma unroll
    for (int i = 0; i < 4; i++) {
        const __nv_bfloat16* src = b_hl[i] ? g_wlo : g_whi;
        rB[i] = *(const uint4*)(src + (size_t)(n0 + b_row[i]) * K5P + b_seg[i] * 8);
    }
    #pragma unroll
    for (int i = 0; i < 2; i++)
        *(uint4*)(sA + ((a_hl[i]) * 64 + a_row[i]) * GSTR + a_seg[i] * 8) = rA[i];
    #pragma unroll
    for (int i = 0; i < 4; i++)
        *(uint4*)(sB + ((b_hl[i]) * 128 + b_row[i]) * GSTR + b_seg[i] * 8) = rB[i];
    __syncthreads();

    for (int c = 0; c < KCH; c++) {
        int buf = c & 1;
        if (c + 1 < KCH) {
            int kb = (c + 1) * 32;
            #pragma unroll
            for (int i = 0; i < 2; i++) {
                const __nv_bfloat16* src = a_hl[i] ? g_glo : g_ghi;
                rA[i] = *(const uint4*)(src + (size_t)(m0 + a_row[i]) * K5P + kb + a_seg[i] * 8);
            }
            #pragma unroll
            for (int i = 0; i < 4; i++) {
                const __nv_bfloat16* src = b_hl[i] ? g_wlo : g_whi;
                rB[i] = *(const uint4*)(src + (size_t)(n0 + b_row[i]) * K5P + kb + b_seg[i] * 8);
            }
        }
        #pragma unroll
        for (int kk = 0; kk < 2; kk++) {
            unsigned a[2][2][4], bf[2][4][2];
            int arow = lane & 15;
            int acol = kk * 16 + ((lane >> 4) << 3);
            #pragma unroll
            for (int hl = 0; hl < 2; hl++)
                #pragma unroll
                for (int mi = 0; mi < 2; mi++) {
                    unsigned ad = sA_u +
                        (((buf * 2 + hl) * 64 + wm * 32 + mi * 16 + arow) * GSTR + acol) * 2;
                    ldm_x4(ad, a[hl][mi][0], a[hl][mi][1], a[hl][mi][2], a[hl][mi][3]);
                }
            int bn = (lane & 7) + ((lane >> 4) & 1) * 8;
            int bk = kk * 16 + (lane & 8);
            #pragma unroll
            for (int hl = 0; hl < 2; hl++)
                #pragma unroll
                for (int ni = 0; ni < 2; ni++) {
                    unsigned r0, r1, r2, r3;
                    unsigned ad = sB_u +
                        (((buf * 2 + hl) * 128 + wn * 32 + ni * 16 + bn) * GSTR + bk) * 2;
                    ldm_x4(ad, r0, r1, r2, r3);
                    bf[hl][2 * ni][0] = r0;     bf[hl][2 * ni][1] = r1;
                    bf[hl][2 * ni + 1][0] = r2; bf[hl][2 * ni + 1][1] = r3;
                }
            #pragma unroll
            for (int mi = 0; mi < 2; mi++)
                #pragma unroll
                for (int j = 0; j < 4; j++) {
                    mma_bf16(d[mi][j], a[0][mi], bf[0][j]);
                    mma_bf16(d[mi][j], a[0][mi], bf[1][j]);
                    mma_bf16(d[mi][j], a[1][mi], bf[0][j]);
                }
        }
        if (c + 1 < KCH) {
            int nb = buf ^ 1;
            #pragma unroll
            for (int i = 0; i < 2; i++)
                *(uint4*)(sA + ((nb * 2 + a_hl[i]) * 64 + a_row[i]) * GSTR + a_seg[i] * 8) = rA[i];
            #pragma unroll
            for (int i = 0; i < 4; i++)
                *(uint4*)(sB + ((nb * 2 + b_hl[i]) * 128 + b_row[i]) * GSTR + b_seg[i] * 8) = rB[i];
        }
        __syncthreads();
    }

    #pragma unroll
    for (int mi = 0; mi < 2; mi++)
        #pragma unroll
        for (int j = 0; j < 4; j++) {
            int row0 = m0 + wm * 32 + mi * 16 + (lane >> 2);
            int col = n0 + wn * 32 + j * 8 + (lane & 3) * 2;
            float bia = bih0[col], bib = bih0[col + 1];
            if (row0 < SB) {
                g_gi0[(size_t)row0 * G3 + col]     = d[mi][j][0] + bia;
                g_gi0[(size_t)row0 * G3 + col + 1] = d[mi][j][1] + bib;
            }
            if (row0 + 8 < SB) {
                g_gi0[(size_t)(row0 + 8) * G3 + col]     = d[mi][j][2] + bia;
                g_gi0[(size_t)(row0 + 8) * G3 + col + 1] = d[mi][j][3] + bib;
            }
        }
}

// ---------------- GRU step pieces (unchanged from R1) ----------------
#define HPAD 514

__device__ void gru_update(const float* __restrict__ gi, const float* __restrict__ hin,
                           float* __restrict__ hout, float* __restrict__ outcopy,
                           const float* __restrict__ whh, const float* __restrict__ bhh,
                           int jtile, float* sm) {
    float* s_h = sm;
    float* s_w = sm + BATCH * HPAD;
    int tid = threadIdx.x;
    for (int e = tid; e < BATCH * HID; e += 256) {
        int b = e >> 9, kk = e & 511;
        s_h[b * HPAD + kk] = hin[e];
    }
    for (int e = tid; e < 3 * 8 * HID; e += 256) {
        int r = e >> 9, kk = e & 511;
        int g = r >> 3, jl = r & 7;
        s_w[r * HID + kk] = whh[((size_t)(g * HID + jtile * 8 + jl)) * HID + kk];
    }
    __syncthreads();
    int b = tid & 31, jl = tid >> 5;
    const unsigned long long* hp = (const unsigned long long*)(s_h + b * HPAD);
    const unsigned long long* wr = (const unsigned long long*)(s_w + (0 * 8 + jl) * HID);
    const unsigned long long* wz = (const unsigned long long*)(s_w + (1 * 8 + jl) * HID);
    const unsigned long long* wn = (const unsigned long long*)(s_w + (2 * 8 + jl) * HID);
    unsigned long long ar = 0ull, az = 0ull, an = 0ull;
    #pragma unroll 8
    for (int q = 0; q < HID / 2; q++) {
        unsigned long long h2 = hp[q];
        FFMA2(ar, h2, wr[q]);
        FFMA2(az, h2, wz[q]);
        FFMA2(an, h2, wn[q]);
    }
    int j = jtile * 8 + jl;
    float ghr = hsum2(ar) + bhh[j];
    float ghz = hsum2(az) + bhh[HID + j];
    float ghn = hsum2(an) + bhh[2 * HID + j];
    float gir = gi[b * G3 + j];
    float giz = gi[b * G3 + HID + j];
    float gin = gi[b * G3 + 2 * HID + j];
    float r = 1.f / (1.f + expf(-(gir + ghr)));
    float z = 1.f / (1.f + expf(-(giz + ghz)));
    float n = tanhf(gin + r * ghn);
    float hprev = s_h[b * HPAD + j];
    float hnew = (1.f - z) * n + z * hprev;
    hout[b * HID + j] = hnew;
    outcopy[b * HID + j] = hnew;
}

__device__ void gemm_gi1(const float* __restrict__ inp, const float* __restrict__ wih,
                         const float* __restrict__ bih, float* __restrict__ gi1,
                         int ctile, float* sm) {
    float* s_in = sm;
    float* s_w = sm + BATCH * HPAD;
    int tid = threadIdx.x;
    for (int e = tid; e < BATCH * HID; e += 256) {
        int b = e >> 9, kk = e & 511;
        s_in[b * HPAD + kk] = inp[e];
    }
    for (int e = tid; e < 32 * HID; e += 256) {
        int r = e >> 9;
        s_w[e] = wih[((size_t)(ctile * 32 + r)) * HID + (e & 511)];
    }
    __syncthreads();
    int b = tid & 31, cg = tid >> 5;
    const unsigned long long* ip = (const unsigned long long*)(s_in + b * HPAD);
    unsigned long long a0 = 0ull, a1 = 0ull, a2 = 0ull, a3 = 0ull;
    const unsigned long long* w0 = (const unsigned long long*)(s_w + (cg * 4 + 0) * HID);
    const unsigned long long* w1 = (const unsigned long long*)(s_w + (cg * 4 + 1) * HID);
    const unsigned long long* w2 = (const unsigned long long*)(s_w + (cg * 4 + 2) * HID);
    const unsigned long long* w3 = (const unsigned long long*)(s_w + (cg * 4 + 3) * HID);
    #pragma unroll 8
    for (int q = 0; q < HID / 2; q++) {
        unsigned long long h2 = ip[q];
        FFMA2(a0, h2, w0[q]);
        FFMA2(a1, h2, w1[q]);
        FFMA2(a2, h2, w2[q]);
        FFMA2(a3, h2, w3[q]);
    }
    int col = ctile * 32 + cg * 4;
    gi1[b * G3 + col + 0] = hsum2(a0) + bih[col + 0];
    gi1[b * G3 + col + 1] = hsum2(a1) + bih[col + 1];
    gi1[b * G3 + col + 2] = hsum2(a2) + bih[col + 2];
    gi1[b * G3 + col + 3] = hsum2(a3) + bih[col + 3];
}

__global__ __launch_bounds__(256) void gru_step_kernel(
        int k,
        const float* __restrict__ w_hh0, const float* __restrict__ b_hh0,
        const float* __restrict__ w_ih1, const float* __restrict__ b_ih1,
        const float* __restrict__ w_hh1, const float* __restrict__ b_hh1,
        float* __restrict__ d_out) {
    extern __shared__ float sm[];
    int cta = blockIdx.x;
    if (cta < 64) {
        if (k >= S) return;
        gru_update(g_gi0 + (size_t)k * BATCH * G3, g_h0[k & 1], g_h0[(k + 1) & 1],
                   g_out1 + (size_t)k * BATCH * HID, w_hh0, b_hh0, cta, sm);
    } else if (cta < 128) {
        int t = k - 2;
        if (t < 0 || t >= S) return;
        gru_update(g_gi1[t & 1], g_h1[t & 1], g_h1[(t + 1) & 1],
                   d_out + (size_t)t * BATCH * HID, w_hh1, b_hh1, cta - 64, sm);
    } else {
        int t = k - 1;
        if (t < 0 || t >= S) return;
        gemm_gi1(g_out1 + (size_t)t * BATCH * HID, w_ih1, b_ih1, g_gi1[t & 1],
                 cta - 128, sm);
    }
}

__global__ void copy_hn_kernel(float* __restrict__ d_out) {
    int i = blockIdx.x * blockDim.x + threadIdx.x;
    if (i < BATCH * HID) {
        d_out[S * BATCH * HID + i] = g_h0[1][i];
        d_out[S * BATCH * HID + BATCH * HID + i] = g_h1[1][i];
    }
}

// ---------------- host launch ----------------
extern "C" void kernel_launch(void* const* d_in, const int* in_sizes, int n_in,
                              void* d_out, int out_size) {
    const float* x     = (const float*)d_in[0];
    const int*   ei    = (const int*)d_in[1];
    const float* W1    = (const float*)d_in[2];
    const float* b1    = (const float*)d_in[3];
    const float* W2    = (const float*)d_in[4];
    const float* b2    = (const float*)d_in[5];
    const float* w_ih0 = (const float*)d_in[6];
    const float* w_hh0 = (const float*)d_in[7];
    const float* b_ih0 = (const float*)d_in[8];
    const float* b_hh0 = (const float*)d_in[9];
    const float* w_ih1 = (const float*)d_in[10];
    const float* w_hh1 = (const float*)d_in[11];
    const float* b_ih1 = (const float*)d_in[12];
    const float* b_hh1 = (const float*)d_in[13];
    float* out = (float*)d_out;

    const int SMEM_GCN  = 2 * 2 * NNODE * (int)sizeof(float);
    const int SMEM_STEP = (BATCH * HPAD + 32 * HID) * (int)sizeof(float);
    const int SMEM_GEMM = SA_BYTES + SB_BYTES;

    cudaFuncSetAttribute(gcn_kernel, cudaFuncAttributeMaxDynamicSharedMemorySize, SMEM_GCN);
    cudaFuncSetAttribute(gru_step_kernel, cudaFuncAttributeMaxDynamicSharedMemorySize, SMEM_STEP);
    cudaFuncSetAttribute(gemm_gi0_kernel, cudaFuncAttributeMaxDynamicSharedMemorySize, SMEM_GEMM);

    init_kernel<<<(BATCH * HID + 255) / 256, 256>>>(ei);
    count_kernel<<<(NEDGE + 255) / 256, 256>>>(ei);
    scan_kernel<<<1, 1024>>>();
    fill_kernel<<<(NEDGE_SL + 255) / 256, 256>>>(ei);
    wconv_kernel<<<(G3 * K5 + 255) / 256, 256>>>(w_ih0);

    gcn_kernel<<<SB, 512, SMEM_GCN>>>(x, W1, b1, W2, b2);
    gemm_gi0_kernel<<<dim3(MP / 64, G3 / 128), 256, SMEM_GEMM>>>(b_ih0);

    for (int k = 0; k < S + 2; k++)
        gru_step_kernel<<<176, 256, SMEM_STEP>>>(k, w_hh0, b_hh0, w_ih1, b_ih1,
                                                 w_hh1, b_hh1, out);

    copy_hn_kernel<<<(BATCH * HID + 255) / 256, 256>>>(out);
}

// round 4
// speedup vs baseline: 2.5865x; 1.9596x over previous
#include <cuda_runtime.h>
#include <cuda_bf16.h>
#include <math.h>

#define S      15
#define BATCH  32
#define NNODE  5000
#define NEDGE  80000
#define NEDGE_SL (NEDGE + NNODE)
#define FIN    16
#define HID    512
#define G3     1536
#define SB     (S*BATCH)
#define K5     5000
#define K5P    5024
#define MP     512
#define KCH    157
#define BH     (BATCH*HID)

typedef unsigned long long ull;

struct __align__(8) Edge { int s; float w; };

__device__ int   g_indeg[NNODE];
__device__ int   g_off[NNODE + 1];
__device__ int   g_pos[NNODE];
__device__ float g_dinv[NNODE];
__device__ Edge  g_edges[NEDGE_SL];
__device__ int   g_is64;

__device__ __nv_bfloat16 g_ghi[MP * K5P];
__device__ __nv_bfloat16 g_glo[MP * K5P];
__device__ __nv_bfloat16 g_whi[G3 * K5P];
__device__ __nv_bfloat16 g_wlo[G3 * K5P];

__device__ float g_gi0[SB * G3];
__device__ float g_gi1[S * BATCH * G3];
__device__ float g_h0s[(S + 1) * BH];
__device__ float g_h1s[(S + 1) * BH];
__device__ int   g_f0[S], g_f1[S], g_f2[S];

#define FFMA2(c, a, b) asm("fma.rn.f32x2 %0, %1, %2, %0;" : "+l"(c) : "l"(a), "l"(b))
__device__ __forceinline__ float hsum2(ull v) {
    float lo, hi;
    asm("mov.b64 {%0,%1}, %2;" : "=f"(lo), "=f"(hi) : "l"(v));
    return lo + hi;
}
__device__ __forceinline__ unsigned smem_u32(const void* p) {
    return (unsigned)__cvta_generic_to_shared(p);
}
__device__ __forceinline__ void ldm_x4(unsigned a, unsigned& r0, unsigned& r1,
                                       unsigned& r2, unsigned& r3) {
    asm volatile("ldmatrix.sync.aligned.m8n8.x4.shared.b16 {%0,%1,%2,%3}, [%4];"
                 : "=r"(r0), "=r"(r1), "=r"(r2), "=r"(r3) : "r"(a));
}
__device__ __forceinline__ void mma_bf16(float* d, const unsigned* a, const unsigned* b) {
    asm volatile(
        "mma.sync.aligned.m16n8k16.row.col.f32.bf16.bf16.f32 "
        "{%0,%1,%2,%3}, {%4,%5,%6,%7}, {%8,%9}, {%0,%1,%2,%3};"
        : "+f"(d[0]), "+f"(d[1]), "+f"(d[2]), "+f"(d[3])
        : "r"(a[0]), "r"(a[1]), "r"(a[2]), "r"(a[3]), "r"(b[0]), "r"(b[1]));
}
__device__ __forceinline__ void spin32(const int* p) {
    int v;
    do {
        asm volatile("ld.acquire.gpu.b32 %0, [%1];" : "=r"(v) : "l"(p));
        if (v < 32) __nanosleep(64);
    } while (v < 32);
}

// ---------------- prep ----------------
__global__ void init_kernel(const int* __restrict__ ei) {
    int i = blockIdx.x * blockDim.x + threadIdx.x;
    if (i < NNODE) g_indeg[i] = 1;
    if (i < BH) { g_h0s[i] = 0.f; g_h1s[i] = 0.f; }
    if (i < S) { g_f0[i] = 0; g_f1[i] = 0; g_f2[i] = 0; }
    if (i == 0) {
        int f = 1;
        for (int q = 0; q < 64; q++) if (ei[2 * q + 1] != 0) { f = 0; break; }
        g_is64 = f;
    }
}
__global__ void count_kernel(const int* __restrict__ ei) {
    int e = blockIdx.x * blockDim.x + threadIdx.x;
    if (e >= NEDGE) return;
    int t = g_is64 ? ei[2 * (NEDGE + e)] : ei[NEDGE + e];
    atomicAdd(&g_indeg[t], 1);
}
__global__ void scan_kernel() {
    __shared__ int ssum[1024];
    int t = threadIdx.x;
    int vals[5]; int s = 0;
    #pragma unroll
    for (int q = 0; q < 5; q++) {
        int idx = t * 5 + q;
        vals[q] = (idx < NNODE) ? g_indeg[idx] : 0;
        s += vals[q];
    }
    ssum[t] = s;
    __syncthreads();
    for (int off = 1; off < 1024; off <<= 1) {
        int v = (t >= off) ? ssum[t - off] : 0;
        __syncthreads();
        ssum[t] += v;
        __syncthreads();
    }
    int run = ssum[t] - s;
    #pragma unroll
    for (int q = 0; q < 5; q++) {
        int idx = t * 5 + q;
        if (idx < NNODE) {
            g_off[idx] = run; g_pos[idx] = run;
            g_dinv[idx] = rsqrtf((float)vals[q]);
            run += vals[q];
        }
    }
    if (t == 1023) g_off[NNODE] = ssum[1023];
}
__global__ void fill_kernel(const int* __restrict__ ei) {
    int e = blockIdx.x * blockDim.x + threadIdx.x;
    if (e >= NEDGE_SL) return;
    int is64 = g_is64;
    int s, t;
    if (e < NEDGE) {
        s = is64 ? ei[2 * e] : ei[e];
        t = is64 ? ei[2 * (NEDGE + e)] : ei[NEDGE + e];
    } else { s = t = e - NEDGE; }
    int idx = atomicAdd(&g_pos[t], 1);
    Edge E; E.s = s; E.w = g_dinv[s] * g_dinv[t];
    g_edges[idx] = E;
}
__global__ void wconv_kernel(const float* __restrict__ wih0) {
    int i = blockIdx.x * blockDim.x + threadIdx.x;
    if (i >= G3 * K5) return;
    int n = i / K5, k = i - n * K5;
    float v = wih0[i];
    __nv_bfloat16 hi = __float2bfloat16(v);
    g_whi[(size_t)n * K5P + k] = hi;
    g_wlo[(size_t)n * K5P + k] = __float2bfloat16(v - __bfloat162float(hi));
}

// ---------------- fused GCN ----------------
__global__ void gcn_kernel(const float* __restrict__ x, const float* __restrict__ W1,
                           const float* __restrict__ b1, const float* __restrict__ W2,
                           const float* __restrict__ b2) {
    extern __shared__ float sm[];
    float* hA = sm;
    float* hB = sm + 2 * NNODE;
    int sb = blockIdx.x;
    int s = sb >> 5;
    int tid = threadIdx.x;

    float w10[FIN], w11[FIN];
    #pragma unroll
    for (int f = 0; f < FIN; f++) {
        w10[f] = W1[s * (FIN * 2) + f * 2 + 0];
        w11[f] = W1[s * (FIN * 2) + f * 2 + 1];
    }
    float b10 = b1[s * 2 + 0], b11 = b1[s * 2 + 1];
    float w20 = W2[s * 2 + 0], w21 = W2[s * 2 + 1];
    float b2s = b2[s];

    const float* xb = x + (size_t)sb * NNODE * FIN;
    for (int n = tid; n < NNODE; n += 512) {
        const float4* xp = (const float4*)(xb + (size_t)n * FIN);
        float xv[16];
        *(float4*)&xv[0] = xp[0]; *(float4*)&xv[4] = xp[1];
        *(float4*)&xv[8] = xp[2]; *(float4*)&xv[12] = xp[3];
        float a0 = 0.f, a1 = 0.f;
        #pragma unroll
        for (int f = 0; f < FIN; f++) { a0 += xv[f] * w10[f]; a1 += xv[f] * w11[f]; }
        hA[2 * n] = a0; hA[2 * n + 1] = a1;
    }
    __syncthreads();
    for (int n = tid; n < NNODE; n += 512) {
        int e0 = g_off[n], e1 = g_off[n + 1];
        float a0 = 0.f, a1 = 0.f;
        for (int e = e0; e < e1; e++) {
            Edge E = g_edges[e];
            a0 += E.w * hA[2 * E.s];
            a1 += E.w * hA[2 * E.s + 1];
        }
        hB[2 * n]     = fmaxf(a0 + b10, 0.f);
        hB[2 * n + 1] = fmaxf(a1 + b11, 0.f);
    }
    __syncthreads();
    for (int n = tid; n < NNODE; n += 512)
        hA[n] = hB[2 * n] * w20 + hB[2 * n + 1] * w21;
    __syncthreads();
    for (int n = tid; n < NNODE; n += 512) {
        int e0 = g_off[n], e1 = g_off[n + 1];
        float q = 0.f;
        for (int e = e0; e < e1; e++) {
            Edge E = g_edges[e];
            q += E.w * hA[E.s];
        }
        float g = tanhf(q + b2s);
        __nv_bfloat16 hi = __float2bfloat16(g);
        g_ghi[(size_t)sb * K5P + n] = hi;
        g_glo[(size_t)sb * K5P + n] = __float2bfloat16(g - __bfloat162float(hi));
    }
}

// ---------------- gi0 GEMM: bf16 split mma ----------------
#define GSTR 72
#define SA_BYTES (2 * 2 * 64 * GSTR * 2)
#define SB_BYTES (2 * 2 * 128 * GSTR * 2)

__global__ __launch_bounds__(256) void gemm_gi0_kernel(const float* __restrict__ bih0) {
    extern __shared__ char smraw[];
    __nv_bfloat16* sA = (__nv_bfloat16*)smraw;
    __nv_bfloat16* sB = (__nv_bfloat16*)(smraw + SA_BYTES);
    unsigned sA_u = smem_u32(sA), sB_u = smem_u32(sB);

    int tid = threadIdx.x;
    int lane = tid & 31, warp = tid >> 5;
    int wm = warp >> 2, wn = warp & 3;
    int m0 = blockIdx.x * 64, n0 = blockIdx.y * 128;

    float d[2][4][4];
    #pragma unroll
    for (int i = 0; i < 2; i++)
        #pragma unroll
        for (int j = 0; j < 4; j++)
            #pragma unroll
            for (int q = 0; q < 4; q++) d[i][j][q] = 0.f;

    int a_hl[2], a_row[2], a_seg[2];
    #pragma unroll
    for (int i = 0; i < 2; i++) {
        int idx = tid + i * 256;
        a_hl[i] = idx >> 8; int r = idx & 255;
        a_row[i] = r >> 2; a_seg[i] = r & 3;
    }
    int b_hl[4], b_row[4], b_seg[4];
    #pragma unroll
    for (int i = 0; i < 4; i++) {
        int idx = tid + i * 256;
        b_hl[i] = idx >> 9; int r = idx & 511;
        b_row[i] = r >> 2; b_seg[i] = r & 3;
    }

    uint4 rA[2], rB[4];
    #pragma unroll
    for (int i = 0; i < 2; i++) {
        const __nv_bfloat16* src = a_hl[i] ? g_glo : g_ghi;
        rA[i] = *(const uint4*)(src + (size_t)(m0 + a_row[i]) * K5P + a_seg[i] * 8);
    }
    #pragma unroll
    for (int i = 0; i < 4; i++) {
        const __nv_bfloat16* src = b_hl[i] ? g_wlo : g_whi;
        rB[i] = *(const uint4*)(src + (size_t)(n0 + b_row[i]) * K5P + b_seg[i] * 8);
    }
    #pragma unroll
    for (int i = 0; i < 2; i++)
        *(uint4*)(sA + ((a_hl[i]) * 64 + a_row[i]) * GSTR + a_seg[i] * 8) = rA[i];
    #pragma unroll
    for (int i = 0; i < 4; i++)
        *(uint4*)(sB + ((b_hl[i]) * 128 + b_row[i]) * GSTR + b_seg[i] * 8) = rB[i];
    __syncthreads();

    for (int c = 0; c < KCH; c++) {
        int buf = c & 1;
        if (c + 1 < KCH) {
            int kb = (c + 1) * 32;
            #pragma unroll
            for (int i = 0; i < 2; i++) {
                const __nv_bfloat16* src = a_hl[i] ? g_glo : g_ghi;
                rA[i] = *(const uint4*)(src + (size_t)(m0 + a_row[i]) * K5P + kb + a_seg[i] * 8);
            }
            #pragma unroll
            for (int i = 0; i < 4; i++) {
                const __nv_bfloat16* src = b_hl[i] ? g_wlo : g_whi;
                rB[i] = *(const uint4*)(src + (size_t)(n0 + b_row[i]) * K5P + kb + b_seg[i] * 8);
            }
        }
        #pragma unroll
        for (int kk = 0; kk < 2; kk++) {
            unsigned a[2][2][4], bf[2][4][2];
            int arow = lane & 15;
            int acol = kk * 16 + ((lane >> 4) << 3);
            #pragma unroll
            for (int hl = 0; hl < 2; hl++)
                #pragma unroll
                for (int mi = 0; mi < 2; mi++) {
                    unsigned ad = sA_u +
                        (((buf * 2 + hl) * 64 + wm * 32 + mi * 16 + arow) * GSTR + acol) * 2;
                    ldm_x4(ad, a[hl][mi][0], a[hl][mi][1], a[hl][mi][2], a[hl][mi][3]);
                }
            int bn = (lane & 7) + ((lane >> 4) & 1) * 8;
            int bk = kk * 16 + (lane & 8);
            #pragma unroll
            for (int hl = 0; hl < 2; hl++)
                #pragma unroll
                for (int ni = 0; ni < 2; ni++) {
                    unsigned r0, r1, r2, r3;
                    unsigned ad = sB_u +
                        (((buf * 2 + hl) * 128 + wn * 32 + ni * 16 + bn) * GSTR + bk) * 2;
                    ldm_x4(ad, r0, r1, r2, r3);
                    bf[hl][2 * ni][0] = r0;     bf[hl][2 * ni][1] = r1;
                    bf[hl][2 * ni + 1][0] = r2; bf[hl][2 * ni + 1][1] = r3;
                }
            #pragma unroll
            for (int mi = 0; mi < 2; mi++)
                #pragma unroll
                for (int j = 0; j < 4; j++) {
                    mma_bf16(d[mi][j], a[0][mi], bf[0][j]);
                    mma_bf16(d[mi][j], a[0][mi], bf[1][j]);
                    mma_bf16(d[mi][j], a[1][mi], bf[0][j]);
                }
        }
        if (c + 1 < KCH) {
            int nb = buf ^ 1;
            #pragma unroll
            for (int i = 0; i < 2; i++)
                *(uint4*)(sA + ((nb * 2 + a_hl[i]) * 64 + a_row[i]) * GSTR + a_seg[i] * 8) = rA[i];
            #pragma unroll
            for (int i = 0; i < 4; i++)
                *(uint4*)(sB + ((nb * 2 + b_hl[i]) * 128 + b_row[i]) * GSTR + b_seg[i] * 8) = rB[i];
        }
        __syncthreads();
    }

    #pragma unroll
    for (int mi = 0; mi < 2; mi++)
        #pragma unroll
        for (int j = 0; j < 4; j++) {
            int row0 = m0 + wm * 32 + mi * 16 + (lane >> 2);
            int col = n0 + wn * 32 + j * 8 + (lane & 3) * 2;
            float bia = bih0[col], bib = bih0[col + 1];
            if (row0 < SB) {
                g_gi0[(size_t)row0 * G3 + col]     = d[mi][j][0] + bia;
                g_gi0[(size_t)row0 * G3 + col + 1] = d[mi][j][1] + bib;
            }
            if (row0 + 8 < SB) {
                g_gi0[(size_t)(row0 + 8) * G3 + col]     = d[mi][j][2] + bia;
                g_gi0[(size_t)(row0 + 8) * G3 + col + 1] = d[mi][j][3] + bib;
            }
        }
}

// ---------------- persistent GRU ----------------
// 96 CTAs x 256 thr. role = bid/32: 0=layer0 update, 1=gi1 gemm, 2=layer1 update.
// smem: s_w[48][512] weights (loaded once), s_h[32][514] staged state.
#define HP 514
#define GRU_SMEM ((48 * 512 + 32 * HP) * 4)

__global__ __launch_bounds__(256, 1) void gru_persist_kernel(
        const float* __restrict__ whh0, const float* __restrict__ bhh0,
        const float* __restrict__ wih1, const float* __restrict__ bih1,
        const float* __restrict__ whh1, const float* __restrict__ bhh1,
        float* __restrict__ d_out) {
    extern __shared__ float sm[];
    float* s_w = sm;
    float* s_h = sm + 48 * 512;
    int tid = threadIdx.x;
    int role = blockIdx.x >> 5;
    int c = blockIdx.x & 31;

    const float* wsrc = (role == 0) ? whh0 : ((role == 1) ? wih1 : whh1);
    for (int e = tid; e < 48 * 512; e += 256) {
        int r = e >> 9, k = e & 511;
        int G = (role == 1) ? (c * 48 + r) : ((r >> 4) * HID + c * 16 + (r & 15));
        s_w[e] = wsrc[(size_t)G * HID + k];
    }

    int bg = tid & 15, jl = tid >> 4;
    const ull* w0 = (const ull*)(s_w + (size_t)jl * 512);
    const ull* w1 = (const ull*)(s_w + (size_t)(16 + jl) * 512);
    const ull* w2 = (const ull*)(s_w + (size_t)(32 + jl) * 512);
    const ull* hp0 = (const ull*)(s_h + (size_t)(2 * bg) * HP);
    const ull* hp1 = (const ull*)(s_h + (size_t)(2 * bg + 1) * HP);

    for (int t = 0; t < S; t++) {
        if (tid == 0) {
            if (role == 0) { if (t) spin32(&g_f0[t - 1]); }
            else if (role == 1) { spin32(&g_f0[t]); }
            else { spin32(&g_f1[t]); if (t) spin32(&g_f2[t - 1]); }
        }
        __syncthreads();

        const float* hsrc = (role == 0) ? (g_h0s + (size_t)t * BH)
                          : (role == 1) ? (g_h0s + (size_t)(t + 1) * BH)
                                        : (g_h1s + (size_t)t * BH);
        for (int e = tid; e < 32 * 128; e += 256) {
            int b = e >> 7, k4 = (e & 127) * 4;
            float4 v = *(const float4*)(hsrc + (size_t)b * HID + k4);
            float* dst = s_h + (size_t)b * HP + k4;
            dst[0] = v.x; dst[1] = v.y; dst[2] = v.z; dst[3] = v.w;
        }
        __syncthreads();

        ull a00 = 0, a01 = 0, a10 = 0, a11 = 0, a20 = 0, a21 = 0;
        #pragma unroll 4
        for (int q = 0; q < 256; q++) {
            ull h0 = hp0[q], h1 = hp1[q];
            ull v0 = w0[q], v1 = w1[q], v2 = w2[q];
            FFMA2(a00, h0, v0); FFMA2(a01, h1, v0);
            FFMA2(a10, h0, v1); FFMA2(a11, h1, v1);
            FFMA2(a20, h0, v2); FFMA2(a21, h1, v2);
        }

        if (role == 1) {
            float* gi = g_gi1 + (size_t)t * BATCH * G3;
            int r0 = c * 48 + jl, r1 = r0 + 16, r2 = r0 + 32;
            int b0 = 2 * bg, b1 = b0 + 1;
            gi[(size_t)b0 * G3 + r0] = hsum2(a00) + bih1[r0];
            gi[(size_t)b1 * G3 + r0] = hsum2(a01) + bih1[r0];
            gi[(size_t)b0 * G3 + r1] = hsum2(a10) + bih1[r1];
            gi[(size_t)b1 * G3 + r1] = hsum2(a11) + bih1[r1];
            gi[(size_t)b0 * G3 + r2] = hsum2(a20) + bih1[r2];
            gi[(size_t)b1 * G3 + r2] = hsum2(a21) + bih1[r2];
        } else {
            int j = c * 16 + jl;
            const float* bhh = (role == 0) ? bhh0 : bhh1;
            const float* gi = ((role == 0) ? g_gi0 : g_gi1) + (size_t)t * BATCH * G3;
            float* hdst = ((role == 0) ? g_h0s : g_h1s) + (size_t)(t + 1) * BH;
            float br = bhh[j], bz = bhh[HID + j], bnn = bhh[2 * HID + j];
            #pragma unroll
            for (int bb = 0; bb < 2; bb++) {
                int b = 2 * bg + bb;
                float ghr = hsum2(bb ? a01 : a00) + br;
                float ghz = hsum2(bb ? a11 : a10) + bz;
                float ghn = hsum2(bb ? a21 : a20) + bnn;
                float gir = gi[(size_t)b * G3 + j];
                float giz = gi[(size_t)b * G3 + HID + j];
                float gin = gi[(size_t)b * G3 + 2 * HID + j];
                float r = 1.f / (1.f + expf(-(gir + ghr)));
                float z = 1.f / (1.f + expf(-(giz + ghz)));
                float n = tanhf(gin + r * ghn);
                float hprev = s_h[(size_t)b * HP + j];
                float hnew = (1.f - z) * n + z * hprev;
                hdst[(size_t)b * HID + j] = hnew;
                if (role == 2) d_out[(size_t)t * BH + b * HID + j] = hnew;
                if (t == S - 1)
                    d_out[(size_t)S * BH + (role == 2 ? BH : 0) + b * HID + j] = hnew;
            }
        }

        __threadfence();
        __syncthreads();
        if (tid == 0) {
            int* f = (role == 0) ? &g_f0[t] : ((role == 1) ? &g_f1[t] : &g_f2[t]);
            atomicAdd(f, 1);
        }
    }
}

// ---------------- host launch ----------------
extern "C" void kernel_launch(void* const* d_in, const int* in_sizes, int n_in,
                              void* d_out, int out_size) {
    const float* x     = (const float*)d_in[0];
    const int*   ei    = (const int*)d_in[1];
    const float* W1    = (const float*)d_in[2];
    const float* b1    = (const float*)d_in[3];
    const float* W2    = (const float*)d_in[4];
    const float* b2    = (const float*)d_in[5];
    const float* w_ih0 = (const float*)d_in[6];
    const float* w_hh0 = (const float*)d_in[7];
    const float* b_ih0 = (const float*)d_in[8];
    const float* b_hh0 = (const float*)d_in[9];
    const float* w_ih1 = (const float*)d_in[10];
    const float* w_hh1 = (const float*)d_in[11];
    const float* b_ih1 = (const float*)d_in[12];
    const float* b_hh1 = (const float*)d_in[13];
    float* out = (float*)d_out;

    const int SMEM_GCN  = 2 * 2 * NNODE * (int)sizeof(float);
    const int SMEM_GEMM = SA_BYTES + SB_BYTES;

    cudaFuncSetAttribute(gcn_kernel, cudaFuncAttributeMaxDynamicSharedMemorySize, SMEM_GCN);
    cudaFuncSetAttribute(gemm_gi0_kernel, cudaFuncAttributeMaxDynamicSharedMemorySize, SMEM_GEMM);
    cudaFuncSetAttribute(gru_persist_kernel, cudaFuncAttributeMaxDynamicSharedMemorySize, GRU_SMEM);

    init_kernel<<<(BH + 255) / 256, 256>>>(ei);
    count_kernel<<<(NEDGE + 255) / 256, 256>>>(ei);
    scan_kernel<<<1, 1024>>>();
    fill_kernel<<<(NEDGE_SL + 255) / 256, 256>>>(ei);
    wconv_kernel<<<(G3 * K5 + 255) / 256, 256>>>(w_ih0);

    gcn_kernel<<<SB, 512, SMEM_GCN>>>(x, W1, b1, W2, b2);
    gemm_gi0_kernel<<<dim3(MP / 64, G3 / 128), 256, SMEM_GEMM>>>(b_ih0);

    gru_persist_kernel<<<96, 256, GRU_SMEM>>>(w_hh0, b_hh0, w_ih1, b_ih1,
                                              w_hh1, b_hh1, out);
}

// round 5
// speedup vs baseline: 2.6148x; 1.0109x over previous
#include <cuda_runtime.h>
#include <cuda_bf16.h>
#include <math.h>

#define S      15
#define BATCH  32
#define NNODE  5000
#define NEDGE  80000
#define NEDGE_SL (NEDGE + NNODE)
#define FIN    16
#define HID    512
#define G3     1536
#define SB     (S*BATCH)
#define K5     5000
#define K5P    5024
#define MP     512
#define KCH    157
#define BH     (BATCH*HID)
#define SLC    3

typedef unsigned long long ull;

struct __align__(8) Edge { int s; float w; };

__device__ int   g_indeg[NNODE];
__device__ int   g_off[NNODE + 1];
__device__ int   g_pos[NNODE];
__device__ float g_dinv[NNODE];
__device__ Edge  g_edges[NEDGE_SL];
__device__ int   g_is64;

__device__ __nv_bfloat16 g_ghi[MP * K5P];
__device__ __nv_bfloat16 g_glo[MP * K5P];
__device__ __nv_bfloat16 g_whi[G3 * K5P];
__device__ __nv_bfloat16 g_wlo[G3 * K5P];

__device__ float g_gi0[SB * G3];
__device__ float g_gi1[S * BATCH * G3];
__device__ float g_h0s[(S + 1) * BH];
__device__ float g_h1s[(S + 1) * BH];
__device__ int   g_f0[S], g_f1[S], g_f2[S];

#define FFMA2(c, a, b) asm("fma.rn.f32x2 %0, %1, %2, %0;" : "+l"(c) : "l"(a), "l"(b))
__device__ __forceinline__ float hsum2(ull v) {
    float lo, hi;
    asm("mov.b64 {%0,%1}, %2;" : "=f"(lo), "=f"(hi) : "l"(v));
    return lo + hi;
}
__device__ __forceinline__ unsigned smem_u32(const void* p) {
    return (unsigned)__cvta_generic_to_shared(p);
}
__device__ __forceinline__ void ldm_x4(unsigned a, unsigned& r0, unsigned& r1,
                                       unsigned& r2, unsigned& r3) {
    asm volatile("ldmatrix.sync.aligned.m8n8.x4.shared.b16 {%0,%1,%2,%3}, [%4];"
                 : "=r"(r0), "=r"(r1), "=r"(r2), "=r"(r3) : "r"(a));
}
__device__ __forceinline__ void mma_bf16(float* d, const unsigned* a, const unsigned* b) {
    asm volatile(
        "mma.sync.aligned.m16n8k16.row.col.f32.bf16.bf16.f32 "
        "{%0,%1,%2,%3}, {%4,%5,%6,%7}, {%8,%9}, {%0,%1,%2,%3};"
        : "+f"(d[0]), "+f"(d[1]), "+f"(d[2]), "+f"(d[3])
        : "r"(a[0]), "r"(a[1]), "r"(a[2]), "r"(a[3]), "r"(b[0]), "r"(b[1]));
}
__device__ __forceinline__ void spin32(const int* p) {
    int v;
    do {
        asm volatile("ld.acquire.gpu.b32 %0, [%1];" : "=r"(v) : "l"(p));
        if (v < 32) __nanosleep(64);
    } while (v < 32);
}

// ---------------- prep ----------------
__global__ void init_kernel(const int* __restrict__ ei) {
    int i = blockIdx.x * blockDim.x + threadIdx.x;
    if (i < NNODE) g_indeg[i] = 1;
    if (i < BH) { g_h0s[i] = 0.f; g_h1s[i] = 0.f; }
    if (i < S) { g_f0[i] = 0; g_f1[i] = 0; g_f2[i] = 0; }
    if (i == 0) {
        int f = 1;
        for (int q = 0; q < 64; q++) if (ei[2 * q + 1] != 0) { f = 0; break; }
        g_is64 = f;
    }
}
__global__ void count_kernel(const int* __restrict__ ei) {
    int e = blockIdx.x * blockDim.x + threadIdx.x;
    if (e >= NEDGE) return;
    int t = g_is64 ? ei[2 * (NEDGE + e)] : ei[NEDGE + e];
    atomicAdd(&g_indeg[t], 1);
}
__global__ void scan_kernel() {
    __shared__ int ssum[1024];
    int t = threadIdx.x;
    int vals[5]; int s = 0;
    #pragma unroll
    for (int q = 0; q < 5; q++) {
        int idx = t * 5 + q;
        vals[q] = (idx < NNODE) ? g_indeg[idx] : 0;
        s += vals[q];
    }
    ssum[t] = s;
    __syncthreads();
    for (int off = 1; off < 1024; off <<= 1) {
        int v = (t >= off) ? ssum[t - off] : 0;
        __syncthreads();
        ssum[t] += v;
        __syncthreads();
    }
    int run = ssum[t] - s;
    #pragma unroll
    for (int q = 0; q < 5; q++) {
        int idx = t * 5 + q;
        if (idx < NNODE) {
            g_off[idx] = run; g_pos[idx] = run;
            g_dinv[idx] = rsqrtf((float)vals[q]);
            run += vals[q];
        }
    }
    if (t == 1023) g_off[NNODE] = ssum[1023];
}
__global__ void fill_kernel(const int* __restrict__ ei) {
    int e = blockIdx.x * blockDim.x + threadIdx.x;
    if (e >= NEDGE_SL) return;
    int is64 = g_is64;
    int s, t;
    if (e < NEDGE) {
        s = is64 ? ei[2 * e] : ei[e];
        t = is64 ? ei[2 * (NEDGE + e)] : ei[NEDGE + e];
    } else { s = t = e - NEDGE; }
    int idx = atomicAdd(&g_pos[t], 1);
    Edge E; E.s = s; E.w = g_dinv[s] * g_dinv[t];
    g_edges[idx] = E;
}
__global__ void wconv_kernel(const float* __restrict__ wih0) {
    int i = blockIdx.x * blockDim.x + threadIdx.x;
    if (i >= G3 * K5) return;
    int n = i / K5, k = i - n * K5;
    float v = wih0[i];
    __nv_bfloat16 hi = __float2bfloat16(v);
    g_whi[(size_t)n * K5P + k] = hi;
    g_wlo[(size_t)n * K5P + k] = __float2bfloat16(v - __bfloat162float(hi));
}

// ---------------- fused GCN: 3 slices per CTA ----------------
// smem: hA[5000][6] (3 slices x 2ch) + h2[5000][3] = 180000 bytes
#define SMEM_GCN ((NNODE * 6 + NNODE * 3) * 4)

__global__ __launch_bounds__(512) void gcn_kernel(const float* __restrict__ x,
                                                  const float* __restrict__ W1,
                                                  const float* __restrict__ b1,
                                                  const float* __restrict__ W2,
                                                  const float* __restrict__ b2) {
    extern __shared__ float sm[];
    float* hA = sm;                 // [n][6]
    float* h2 = sm + NNODE * 6;     // [n][3]
    __shared__ float s_w1[SLC][FIN][2];
    __shared__ float s_b1[SLC][2], s_w2[SLC][2], s_b2[SLC];

    int cta = blockIdx.x, tid = threadIdx.x;

    if (tid < SLC * FIN * 2) {
        int sl = tid / (FIN * 2), rem = tid % (FIN * 2);
        int s = (cta * SLC + sl) >> 5;
        s_w1[sl][rem >> 1][rem & 1] = W1[s * (FIN * 2) + rem];
    }
    if (tid >= 128 && tid < 128 + SLC * 2) {
        int q = tid - 128; int sl = q >> 1, c = q & 1;
        int s = (cta * SLC + sl) >> 5;
        s_b1[sl][c] = b1[s * 2 + c];
        s_w2[sl][c] = W2[s * 2 + c];
    }
    if (tid >= 160 && tid < 160 + SLC) {
        int sl = tid - 160;
        s_b2[sl] = b2[((cta * SLC + sl) >> 5)];
    }
    __syncthreads();

    // phase 1: linear per slice
    for (int idx = tid; idx < SLC * NNODE; idx += 512) {
        int sl = idx / NNODE, n = idx - sl * NNODE;
        const float4* xp = (const float4*)(x + ((size_t)(cta * SLC + sl) * NNODE + n) * FIN);
        float xv[16];
        *(float4*)&xv[0] = xp[0]; *(float4*)&xv[4] = xp[1];
        *(float4*)&xv[8] = xp[2]; *(float4*)&xv[12] = xp[3];
        float a0 = 0.f, a1 = 0.f;
        #pragma unroll
        for (int f = 0; f < FIN; f++) {
            a0 += xv[f] * s_w1[sl][f][0];
            a1 += xv[f] * s_w1[sl][f][1];
        }
        hA[n * 6 + sl * 2]     = a0;
        hA[n * 6 + sl * 2 + 1] = a1;
    }
    __syncthreads();

    // phase 2: propagate1 + bias + relu + linear2 -> h2
    for (int n = tid; n < NNODE; n += 512) {
        int e0 = g_off[n], e1 = g_off[n + 1];
        float ac0 = 0.f, ac1 = 0.f, ac2 = 0.f, ac3 = 0.f, ac4 = 0.f, ac5 = 0.f;
        for (int e = e0; e < e1; e++) {
            Edge E = g_edges[e];
            const float2* src = (const float2*)(hA + E.s * 6);
            float2 p0 = src[0], p1 = src[1], p2 = src[2];
            ac0 += E.w * p0.x; ac1 += E.w * p0.y;
            ac2 += E.w * p1.x; ac3 += E.w * p1.y;
            ac4 += E.w * p2.x; ac5 += E.w * p2.y;
        }
        float r0, r1;
        r0 = fmaxf(ac0 + s_b1[0][0], 0.f); r1 = fmaxf(ac1 + s_b1[0][1], 0.f);
        h2[n * 3 + 0] = r0 * s_w2[0][0] + r1 * s_w2[0][1];
        r0 = fmaxf(ac2 + s_b1[1][0], 0.f); r1 = fmaxf(ac3 + s_b1[1][1], 0.f);
        h2[n * 3 + 1] = r0 * s_w2[1][0] + r1 * s_w2[1][1];
        r0 = fmaxf(ac4 + s_b1[2][0], 0.f); r1 = fmaxf(ac5 + s_b1[2][1], 0.f);
        h2[n * 3 + 2] = r0 * s_w2[2][0] + r1 * s_w2[2][1];
    }
    __syncthreads();

    // phase 3: propagate2 + bias + tanh -> bf16 hi/lo
    for (int n = tid; n < NNODE; n += 512) {
        int e0 = g_off[n], e1 = g_off[n + 1];
        float a0 = 0.f, a1 = 0.f, a2 = 0.f;
        for (int e = e0; e < e1; e++) {
            Edge E = g_edges[e];
            const float* src = h2 + E.s * 3;
            a0 += E.w * src[0];
            a1 += E.w * src[1];
            a2 += E.w * src[2];
        }
        float gv[3] = { tanhf(a0 + s_b2[0]), tanhf(a1 + s_b2[1]), tanhf(a2 + s_b2[2]) };
        #pragma unroll
        for (int sl = 0; sl < SLC; sl++) {
            int sb = cta * SLC + sl;
            __nv_bfloat16 hi = __float2bfloat16(gv[sl]);
            g_ghi[(size_t)sb * K5P + n] = hi;
            g_glo[(size_t)sb * K5P + n] = __float2bfloat16(gv[sl] - __bfloat162float(hi));
        }
    }
}

// ---------------- gi0 GEMM: bf16 split mma ----------------
#define GSTR 72
#define SA_BYTES (2 * 2 * 64 * GSTR * 2)
#define SB_BYTES (2 * 2 * 128 * GSTR * 2)

__global__ __launch_bounds__(256) void gemm_gi0_kernel(const float* __restrict__ bih0) {
    extern __shared__ char smraw[];
    __nv_bfloat16* sA = (__nv_bfloat16*)smraw;
    __nv_bfloat16* sB = (__nv_bfloat16*)(smraw + SA_BYTES);
    unsigned sA_u = smem_u32(sA), sB_u = smem_u32(sB);

    int tid = threadIdx.x;
    int lane = tid & 31, warp = tid >> 5;
    int wm = warp >> 2, wn = warp & 3;
    int m0 = blockIdx.x * 64, n0 = blockIdx.y * 128;

    float d[2][4][4];
    #pragma unroll
    for (int i = 0; i < 2; i++)
        #pragma unroll
        for (int j = 0; j < 4; j++)
            #pragma unroll
            for (int q = 0; q < 4; q++) d[i][j][q] = 0.f;

    int a_hl[2], a_row[2], a_seg[2];
    #pragma unroll
    for (int i = 0; i < 2; i++) {
        int idx = tid + i * 256;
        a_hl[i] = idx >> 8; int r = idx & 255;
        a_row[i] = r >> 2; a_seg[i] = r & 3;
    }
    int b_hl[4], b_row[4], b_seg[4];
    #pragma unroll
    for (int i = 0; i < 4; i++) {
        int idx = tid + i * 256;
        b_hl[i] = idx >> 9; int r = idx & 511;
        b_row[i] = r >> 2; b_seg[i] = r & 3;
    }

    uint4 rA[2], rB[4];
    #pragma unroll
    for (int i = 0; i < 2; i++) {
        const __nv_bfloat16* src = a_hl[i] ? g_glo : g_ghi;
        rA[i] = *(const uint4*)(src + (size_t)(m0 + a_row[i]) * K5P + a_seg[i] * 8);
    }
    #pragma unroll
    for (int i = 0; i < 4; i++) {
        const __nv_bfloat16* src = b_hl[i] ? g_wlo : g_whi;
        rB[i] = *(const uint4*)(src + (size_t)(n0 + b_row[i]) * K5P + b_seg[i] * 8);
    }
    #pragma unroll
    for (int i = 0; i < 2; i++)
        *(uint4*)(sA + ((a_hl[i]) * 64 + a_row[i]) * GSTR + a_seg[i] * 8) = rA[i];
    #pragma unroll
    for (int i = 0; i < 4; i++)
        *(uint4*)(sB + ((b_hl[i]) * 128 + b_row[i]) * GSTR + b_seg[i] * 8) = rB[i];
    __syncthreads();

    for (int c = 0; c < KCH; c++) {
        int buf = c & 1;
        if (c + 1 < KCH) {
            int kb = (c + 1) * 32;
            #pragma unroll
            for (int i = 0; i < 2; i++) {
                const __nv_bfloat16* src = a_hl[i] ? g_glo : g_ghi;
                rA[i] = *(const uint4*)(src + (size_t)(m0 + a_row[i]) * K5P + kb + a_seg[i] * 8);
            }
            #pragma unroll
            for (int i = 0; i < 4; i++) {
                const __nv_bfloat16* src = b_hl[i] ? g_wlo : g_whi;
                rB[i] = *(const uint4*)(src + (size_t)(n0 + b_row[i]) * K5P + kb + b_seg[i] * 8);
            }
        }
        #pragma unroll
        for (int kk = 0; kk < 2; kk++) {
            unsigned a[2][2][4], bf[2][4][2];
            int arow = lane & 15;
            int acol = kk * 16 + ((lane >> 4) << 3);
            #pragma unroll
            for (int hl = 0; hl < 2; hl++)
                #pragma unroll
                for (int mi = 0; mi < 2; mi++) {
                    unsigned ad = sA_u +
                        (((buf * 2 + hl) * 64 + wm * 32 + mi * 16 + arow) * GSTR + acol) * 2;
                    ldm_x4(ad, a[hl][mi][0], a[hl][mi][1], a[hl][mi][2], a[hl][mi][3]);
                }
            int bn = (lane & 7) + ((lane >> 4) & 1) * 8;
            int bk = kk * 16 + (lane & 8);
            #pragma unroll
            for (int hl = 0; hl < 2; hl++)
                #pragma unroll
                for (int ni = 0; ni < 2; ni++) {
                    unsigned r0, r1, r2, r3;
                    unsigned ad = sB_u +
                        (((buf * 2 + hl) * 128 + wn * 32 + ni * 16 + bn) * GSTR + bk) * 2;
                    ldm_x4(ad, r0, r1, r2, r3);
                    bf[hl][2 * ni][0] = r0;     bf[hl][2 * ni][1] = r1;
                    bf[hl][2 * ni + 1][0] = r2; bf[hl][2 * ni + 1][1] = r3;
                }
            #pragma unroll
            for (int mi = 0; mi < 2; mi++)
                #pragma unroll
                for (int j = 0; j < 4; j++) {
                    mma_bf16(d[mi][j], a[0][mi], bf[0][j]);
                    mma_bf16(d[mi][j], a[0][mi], bf[1][j]);
                    mma_bf16(d[mi][j], a[1][mi], bf[0][j]);
                }
        }
        if (c + 1 < KCH) {
            int nb = buf ^ 1;
            #pragma unroll
            for (int i = 0; i < 2; i++)
                *(uint4*)(sA + ((nb * 2 + a_hl[i]) * 64 + a_row[i]) * GSTR + a_seg[i] * 8) = rA[i];
            #pragma unroll
            for (int i = 0; i < 4; i++)
                *(uint4*)(sB + ((nb * 2 + b_hl[i]) * 128 + b_row[i]) * GSTR + b_seg[i] * 8) = rB[i];
        }
        __syncthreads();
    }

    #pragma unroll
    for (int mi = 0; mi < 2; mi++)
        #pragma unroll
        for (int j = 0; j < 4; j++) {
            int row0 = m0 + wm * 32 + mi * 16 + (lane >> 2);
            int col = n0 + wn * 32 + j * 8 + (lane & 3) * 2;
            float bia = bih0[col], bib = bih0[col + 1];
            if (row0 < SB) {
                g_gi0[(size_t)row0 * G3 + col]     = d[mi][j][0] + bia;
                g_gi0[(size_t)row0 * G3 + col + 1] = d[mi][j][1] + bib;
            }
            if (row0 + 8 < SB) {
                g_gi0[(size_t)(row0 + 8) * G3 + col]     = d[mi][j][2] + bia;
                g_gi0[(size_t)(row0 + 8) * G3 + col + 1] = d[mi][j][3] + bib;
            }
        }
}

// ---------------- persistent GRU ----------------
#define HP 514
#define GRU_SMEM ((48 * 512 + 32 * HP) * 4)

__global__ __launch_bounds__(256, 1) void gru_persist_kernel(
        const float* __restrict__ whh0, const float* __restrict__ bhh0,
        const float* __restrict__ wih1, const float* __restrict__ bih1,
        const float* __restrict__ whh1, const float* __restrict__ bhh1,
        float* __restrict__ d_out) {
    extern __shared__ float sm[];
    float* s_w = sm;
    float* s_h = sm + 48 * 512;
    int tid = threadIdx.x;
    int role = blockIdx.x >> 5;
    int c = blockIdx.x & 31;

    const float* wsrc = (role == 0) ? whh0 : ((role == 1) ? wih1 : whh1);
    for (int e = tid; e < 48 * 512; e += 256) {
        int r = e >> 9, k = e & 511;
        int G = (role == 1) ? (c * 48 + r) : ((r >> 4) * HID + c * 16 + (r & 15));
        s_w[e] = wsrc[(size_t)G * HID + k];
    }

    int bg = tid & 15, jl = tid >> 4;
    const ull* w0 = (const ull*)(s_w + (size_t)jl * 512);
    const ull* w1 = (const ull*)(s_w + (size_t)(16 + jl) * 512);
    const ull* w2 = (const ull*)(s_w + (size_t)(32 + jl) * 512);
    const ull* hp0 = (const ull*)(s_h + (size_t)(2 * bg) * HP);
    const ull* hp1 = (const ull*)(s_h + (size_t)(2 * bg + 1) * HP);

    for (int t = 0; t < S; t++) {
        if (tid == 0) {
            if (role == 0) { if (t) spin32(&g_f0[t - 1]); }
            else if (role == 1) { spin32(&g_f0[t]); }
            else { spin32(&g_f1[t]); if (t) spin32(&g_f2[t - 1]); }
        }
        __syncthreads();

        const float* hsrc = (role == 0) ? (g_h0s + (size_t)t * BH)
                          : (role == 1) ? (g_h0s + (size_t)(t + 1) * BH)
                                        : (g_h1s + (size_t)t * BH);
        for (int e = tid; e < 32 * 128; e += 256) {
            int b = e >> 7, k4 = (e & 127) * 4;
            float4 v = *(const float4*)(hsrc + (size_t)b * HID + k4);
            float* dst = s_h + (size_t)b * HP + k4;
            dst[0] = v.x; dst[1] = v.y; dst[2] = v.z; dst[3] = v.w;
        }
        __syncthreads();

        ull a00 = 0, a01 = 0, a10 = 0, a11 = 0, a20 = 0, a21 = 0;
        #pragma unroll 4
        for (int q = 0; q < 256; q++) {
            ull h0 = hp0[q], h1 = hp1[q];
            ull v0 = w0[q], v1 = w1[q], v2 = w2[q];
            FFMA2(a00, h0, v0); FFMA2(a01, h1, v0);
            FFMA2(a10, h0, v1); FFMA2(a11, h1, v1);
            FFMA2(a20, h0, v2); FFMA2(a21, h1, v2);
        }

        if (role == 1) {
            float* gi = g_gi1 + (size_t)t * BATCH * G3;
            int r0 = c * 48 + jl, r1 = r0 + 16, r2 = r0 + 32;
            int b0 = 2 * bg, b1 = b0 + 1;
            gi[(size_t)b0 * G3 + r0] = hsum2(a00) + bih1[r0];
            gi[(size_t)b1 * G3 + r0] = hsum2(a01) + bih1[r0];
            gi[(size_t)b0 * G3 + r1] = hsum2(a10) + bih1[r1];
            gi[(size_t)b1 * G3 + r1] = hsum2(a11) + bih1[r1];
            gi[(size_t)b0 * G3 + r2] = hsum2(a20) + bih1[r2];
            gi[(size_t)b1 * G3 + r2] = hsum2(a21) + bih1[r2];
        } else {
            int j = c * 16 + jl;
            const float* bhh = (role == 0) ? bhh0 : bhh1;
            const float* gi = ((role == 0) ? g_gi0 : g_gi1) + (size_t)t * BATCH * G3;
            float* hdst = ((role == 0) ? g_h0s : g_h1s) + (size_t)(t + 1) * BH;
            float br = bhh[j], bz = bhh[HID + j], bnn = bhh[2 * HID + j];
            #pragma unroll
            for (int bb = 0; bb < 2; bb++) {
                int b = 2 * bg + bb;
                float ghr = hsum2(bb ? a01 : a00) + br;
                float ghz = hsum2(bb ? a11 : a10) + bz;
                float ghn = hsum2(bb ? a21 : a20) + bnn;
                float gir = gi[(size_t)b * G3 + j];
                float giz = gi[(size_t)b * G3 + HID + j];
                float gin = gi[(size_t)b * G3 + 2 * HID + j];
                float r = 1.f / (1.f + expf(-(gir + ghr)));
                float z = 1.f / (1.f + expf(-(giz + ghz)));
                float n = tanhf(gin + r * ghn);
                float hprev = s_h[(size_t)b * HP + j];
                float hnew = (1.f - z) * n + z * hprev;
                hdst[(size_t)b * HID + j] = hnew;
                if (role == 2) d_out[(size_t)t * BH + b * HID + j] = hnew;
                if (t == S - 1)
                    d_out[(size_t)S * BH + (role == 2 ? BH : 0) + b * HID + j] = hnew;
            }
        }

        __threadfence();
        __syncthreads();
        if (tid == 0) {
            int* f = (role == 0) ? &g_f0[t] : ((role == 1) ? &g_f1[t] : &g_f2[t]);
            atomicAdd(f, 1);
        }
    }
}

// ---------------- host launch ----------------
extern "C" void kernel_launch(void* const* d_in, const int* in_sizes, int n_in,
                              void* d_out, int out_size) {
    const float* x     = (const float*)d_in[0];
    const int*   ei    = (const int*)d_in[1];
    const float* W1    = (const float*)d_in[2];
    const float* b1    = (const float*)d_in[3];
    const float* W2    = (const float*)d_in[4];
    const float* b2    = (const float*)d_in[5];
    const float* w_ih0 = (const float*)d_in[6];
    const float* w_hh0 = (const float*)d_in[7];
    const float* b_ih0 = (const float*)d_in[8];
    const float* b_hh0 = (const float*)d_in[9];
    const float* w_ih1 = (const float*)d_in[10];
    const float* w_hh1 = (const float*)d_in[11];
    const float* b_ih1 = (const float*)d_in[12];
    const float* b_hh1 = (const float*)d_in[13];
    float* out = (float*)d_out;

    const int SMEM_GEMM = SA_BYTES + SB_BYTES;

    cudaFuncSetAttribute(gcn_kernel, cudaFuncAttributeMaxDynamicSharedMemorySize, SMEM_GCN);
    cudaFuncSetAttribute(gemm_gi0_kernel, cudaFuncAttributeMaxDynamicSharedMemorySize, SMEM_GEMM);
    cudaFuncSetAttribute(gru_persist_kernel, cudaFuncAttributeMaxDynamicSharedMemorySize, GRU_SMEM);

    init_kernel<<<(BH + 255) / 256, 256>>>(ei);
    count_kernel<<<(NEDGE + 255) / 256, 256>>>(ei);
    scan_kernel<<<1, 1024>>>();
    fill_kernel<<<(NEDGE_SL + 255) / 256, 256>>>(ei);
    wconv_kernel<<<(G3 * K5 + 255) / 256, 256>>>(w_ih0);

    gcn_kernel<<<SB / SLC, 512, SMEM_GCN>>>(x, W1, b1, W2, b2);
    gemm_gi0_kernel<<<dim3(MP / 64, G3 / 128), 256, SMEM_GEMM>>>(b_ih0);

    gru_persist_kernel<<<96, 256, GRU_SMEM>>>(w_hh0, b_hh0, w_ih1, b_ih1,
                                              w_hh1, b_hh1, out);
}

// round 6
// speedup vs baseline: 2.6176x; 1.0011x over previous
#include <cuda_runtime.h>
#include <cuda_bf16.h>
#include <math.h>

#define S      15
#define BATCH  32
#define NNODE  5000
#define NEDGE  80000
#define NEDGE_SL (NEDGE + NNODE)
#define FIN    16
#define HID    512
#define G3     1536
#define SB     (S*BATCH)
#define K5     5000
#define K5P    5024
#define MP     512
#define KCH    157
#define BH     (BATCH*HID)
#define SLC    3

typedef unsigned long long ull;

struct __align__(8) Edge { int s; float w; };

__device__ int   g_indeg[NNODE];
__device__ int   g_off[NNODE + 1];
__device__ int   g_pos[NNODE];
__device__ float g_dinv[NNODE];
__device__ Edge  g_edges[NEDGE_SL];
__device__ int   g_is64;

__device__ __nv_bfloat16 g_ghi[MP * K5P];
__device__ __nv_bfloat16 g_glo[MP * K5P];
__device__ __nv_bfloat16 g_whi[G3 * K5P];
__device__ __nv_bfloat16 g_wlo[G3 * K5P];

__device__ float g_gi0[SB * G3];
__device__ float g_gi1[S * BATCH * G3];
__device__ float g_h0s[(S + 1) * BH];
__device__ float g_h1s[(S + 1) * BH];
__device__ int   g_f0[S], g_f1[S], g_f2[S];

#define FFMA2(c, a, b) asm("fma.rn.f32x2 %0, %1, %2, %0;" : "+l"(c) : "l"(a), "l"(b))
__device__ __forceinline__ float hsum2(ull v) {
    float lo, hi;
    asm("mov.b64 {%0,%1}, %2;" : "=f"(lo), "=f"(hi) : "l"(v));
    return lo + hi;
}
__device__ __forceinline__ unsigned smem_u32(const void* p) {
    return (unsigned)__cvta_generic_to_shared(p);
}
__device__ __forceinline__ void ldm_x4(unsigned a, unsigned& r0, unsigned& r1,
                                       unsigned& r2, unsigned& r3) {
    asm volatile("ldmatrix.sync.aligned.m8n8.x4.shared.b16 {%0,%1,%2,%3}, [%4];"
                 : "=r"(r0), "=r"(r1), "=r"(r2), "=r"(r3) : "r"(a));
}
__device__ __forceinline__ void mma_bf16(float* d, const unsigned* a, const unsigned* b) {
    asm volatile(
        "mma.sync.aligned.m16n8k16.row.col.f32.bf16.bf16.f32 "
        "{%0,%1,%2,%3}, {%4,%5,%6,%7}, {%8,%9}, {%0,%1,%2,%3};"
        : "+f"(d[0]), "+f"(d[1]), "+f"(d[2]), "+f"(d[3])
        : "r"(a[0]), "r"(a[1]), "r"(a[2]), "r"(a[3]), "r"(b[0]), "r"(b[1]));
}
__device__ __forceinline__ void spin32(const int* p) {
    int v;
    do {
        asm volatile("ld.acquire.gpu.b32 %0, [%1];" : "=r"(v) : "l"(p));
        if (v < 32) __nanosleep(64);
    } while (v < 32);
}
__device__ __forceinline__ void red_release(int* p) {
    asm volatile("red.release.gpu.global.add.s32 [%0], %1;" :: "l"(p), "r"(1) : "memory");
}

// ---------------- prep ----------------
__global__ void init_kernel(const int* __restrict__ ei) {
    int i = blockIdx.x * blockDim.x + threadIdx.x;
    if (i < NNODE) g_indeg[i] = 1;
    if (i < BH) { g_h0s[i] = 0.f; g_h1s[i] = 0.f; }
    if (i < S) { g_f0[i] = 0; g_f1[i] = 0; g_f2[i] = 0; }
    if (i == 0) {
        int f = 1;
        for (int q = 0; q < 64; q++) if (ei[2 * q + 1] != 0) { f = 0; break; }
        g_is64 = f;
    }
}
__global__ void count_kernel(const int* __restrict__ ei) {
    int e = blockIdx.x * blockDim.x + threadIdx.x;
    if (e >= NEDGE) return;
    int t = g_is64 ? ei[2 * (NEDGE + e)] : ei[NEDGE + e];
    atomicAdd(&g_indeg[t], 1);
}
__global__ void scan_kernel() {
    __shared__ int ssum[1024];
    int t = threadIdx.x;
    int vals[5]; int s = 0;
    #pragma unroll
    for (int q = 0; q < 5; q++) {
        int idx = t * 5 + q;
        vals[q] = (idx < NNODE) ? g_indeg[idx] : 0;
        s += vals[q];
    }
    ssum[t] = s;
    __syncthreads();
    for (int off = 1; off < 1024; off <<= 1) {
        int v = (t >= off) ? ssum[t - off] : 0;
        __syncthreads();
        ssum[t] += v;
        __syncthreads();
    }
    int run = ssum[t] - s;
    #pragma unroll
    for (int q = 0; q < 5; q++) {
        int idx = t * 5 + q;
        if (idx < NNODE) {
            g_off[idx] = run; g_pos[idx] = run;
            g_dinv[idx] = rsqrtf((float)vals[q]);
            run += vals[q];
        }
    }
    if (t == 1023) g_off[NNODE] = ssum[1023];
}
__global__ void fill_kernel(const int* __restrict__ ei) {
    int e = blockIdx.x * blockDim.x + threadIdx.x;
    if (e >= NEDGE_SL) return;
    int is64 = g_is64;
    int s, t;
    if (e < NEDGE) {
        s = is64 ? ei[2 * e] : ei[e];
        t = is64 ? ei[2 * (NEDGE + e)] : ei[NEDGE + e];
    } else { s = t = e - NEDGE; }
    int idx = atomicAdd(&g_pos[t], 1);
    Edge E; E.s = s; E.w = g_dinv[s] * g_dinv[t];
    g_edges[idx] = E;
}
__global__ void wconv_kernel(const float* __restrict__ wih0) {
    int i = blockIdx.x * blockDim.x + threadIdx.x;
    if (i >= G3 * K5) return;
    int n = i / K5, k = i - n * K5;
    float v = wih0[i];
    __nv_bfloat16 hi = __float2bfloat16(v);
    g_whi[(size_t)n * K5P + k] = hi;
    g_wlo[(size_t)n * K5P + k] = __float2bfloat16(v - __bfloat162float(hi));
}

// ---------------- fused GCN: 3 slices per CTA, warp-segmented edge walk ----------------
#define SMEM_GCN ((NNODE * 6 + NNODE * 3) * 4)

__global__ __launch_bounds__(1024) void gcn_kernel(const float* __restrict__ x,
                                                   const float* __restrict__ W1,
                                                   const float* __restrict__ b1,
                                                   const float* __restrict__ W2,
                                                   const float* __restrict__ b2) {
    extern __shared__ float sm[];
    float* hA = sm;                 // [n][6]
    float* h2 = sm + NNODE * 6;     // [n][3]
    __shared__ float s_w1[SLC][FIN][2];
    __shared__ float s_b1[SLC][2], s_w2[SLC][2], s_b2[SLC];

    int cta = blockIdx.x, tid = threadIdx.x;

    if (tid < SLC * FIN * 2) {
        int sl = tid / (FIN * 2), rem = tid % (FIN * 2);
        int s = (cta * SLC + sl) >> 5;
        s_w1[sl][rem >> 1][rem & 1] = W1[s * (FIN * 2) + rem];
    }
    if (tid >= 128 && tid < 128 + SLC * 2) {
        int q = tid - 128; int sl = q >> 1, c = q & 1;
        int s = (cta * SLC + sl) >> 5;
        s_b1[sl][c] = b1[s * 2 + c];
        s_w2[sl][c] = W2[s * 2 + c];
    }
    if (tid >= 160 && tid < 160 + SLC) {
        int sl = tid - 160;
        s_b2[sl] = b2[((cta * SLC + sl) >> 5)];
    }
    __syncthreads();

    // phase 1: linear per slice
    for (int idx = tid; idx < SLC * NNODE; idx += 1024) {
        int sl = idx / NNODE, n = idx - sl * NNODE;
        const float4* xp = (const float4*)(x + ((size_t)(cta * SLC + sl) * NNODE + n) * FIN);
        float xv[16];
        *(float4*)&xv[0] = xp[0]; *(float4*)&xv[4] = xp[1];
        *(float4*)&xv[8] = xp[2]; *(float4*)&xv[12] = xp[3];
        float a0 = 0.f, a1 = 0.f;
        #pragma unroll
        for (int f = 0; f < FIN; f++) {
            a0 += xv[f] * s_w1[sl][f][0];
            a1 += xv[f] * s_w1[sl][f][1];
        }
        hA[n * 6 + sl * 2]     = a0;
        hA[n * 6 + sl * 2 + 1] = a1;
    }
    __syncthreads();

    int warp = tid >> 5, lane = tid & 31;
    int seg = lane >> 3, sub = lane & 7;    // 4 nodes/warp, 8 lanes/node

    // phase 2: propagate1 + bias + relu + linear2 -> h2 (warp-segmented)
    for (int n0 = warp * 4; n0 < NNODE; n0 += 128) {
        int n = n0 + seg;
        int e0 = g_off[n], e1 = g_off[n + 1];
        float ac0 = 0.f, ac1 = 0.f, ac2 = 0.f, ac3 = 0.f, ac4 = 0.f, ac5 = 0.f;
        for (int e = e0 + sub; e < e1; e += 8) {
            Edge E = g_edges[e];
            const float2* src = (const float2*)(hA + E.s * 6);
            float2 p0 = src[0], p1 = src[1], p2 = src[2];
            ac0 += E.w * p0.x; ac1 += E.w * p0.y;
            ac2 += E.w * p1.x; ac3 += E.w * p1.y;
            ac4 += E.w * p2.x; ac5 += E.w * p2.y;
        }
        #pragma unroll
        for (int m = 4; m >= 1; m >>= 1) {
            ac0 += __shfl_xor_sync(0xFFFFFFFF, ac0, m);
            ac1 += __shfl_xor_sync(0xFFFFFFFF, ac1, m);
            ac2 += __shfl_xor_sync(0xFFFFFFFF, ac2, m);
            ac3 += __shfl_xor_sync(0xFFFFFFFF, ac3, m);
            ac4 += __shfl_xor_sync(0xFFFFFFFF, ac4, m);
            ac5 += __shfl_xor_sync(0xFFFFFFFF, ac5, m);
        }
        if (sub == 0) {
            float r0, r1;
            r0 = fmaxf(ac0 + s_b1[0][0], 0.f); r1 = fmaxf(ac1 + s_b1[0][1], 0.f);
            h2[n * 3 + 0] = r0 * s_w2[0][0] + r1 * s_w2[0][1];
            r0 = fmaxf(ac2 + s_b1[1][0], 0.f); r1 = fmaxf(ac3 + s_b1[1][1], 0.f);
            h2[n * 3 + 1] = r0 * s_w2[1][0] + r1 * s_w2[1][1];
            r0 = fmaxf(ac4 + s_b1[2][0], 0.f); r1 = fmaxf(ac5 + s_b1[2][1], 0.f);
            h2[n * 3 + 2] = r0 * s_w2[2][0] + r1 * s_w2[2][1];
        }
    }
    __syncthreads();

    // phase 3: propagate2 + bias + tanh -> bf16 hi/lo (warp-segmented)
    for (int n0 = warp * 4; n0 < NNODE; n0 += 128) {
        int n = n0 + seg;
        int e0 = g_off[n], e1 = g_off[n + 1];
        float a0 = 0.f, a1 = 0.f, a2 = 0.f;
        for (int e = e0 + sub; e < e1; e += 8) {
            Edge E = g_edges[e];
            const float* src = h2 + E.s * 3;
            a0 += E.w * src[0];
            a1 += E.w * src[1];
            a2 += E.w * src[2];
        }
        #pragma unroll
        for (int m = 4; m >= 1; m >>= 1) {
            a0 += __shfl_xor_sync(0xFFFFFFFF, a0, m);
            a1 += __shfl_xor_sync(0xFFFFFFFF, a1, m);
            a2 += __shfl_xor_sync(0xFFFFFFFF, a2, m);
        }
        if (sub == 0) {
            float gv[3] = { tanhf(a0 + s_b2[0]), tanhf(a1 + s_b2[1]), tanhf(a2 + s_b2[2]) };
            #pragma unroll
            for (int sl = 0; sl < SLC; sl++) {
                int sb = cta * SLC + sl;
                __nv_bfloat16 hi = __float2bfloat16(gv[sl]);
                g_ghi[(size_t)sb * K5P + n] = hi;
                g_glo[(size_t)sb * K5P + n] = __float2bfloat16(gv[sl] - __bfloat162float(hi));
            }
        }
    }
}

// ---------------- gi0 GEMM: bf16 split mma ----------------
#define GSTR 72
#define SA_BYTES (2 * 2 * 64 * GSTR * 2)
#define SB_BYTES (2 * 2 * 128 * GSTR * 2)

__global__ __launch_bounds__(256) void gemm_gi0_kernel(const float* __restrict__ bih0) {
    extern __shared__ char smraw[];
    __nv_bfloat16* sA = (__nv_bfloat16*)smraw;
    __nv_bfloat16* sB = (__nv_bfloat16*)(smraw + SA_BYTES);
    unsigned sA_u = smem_u32(sA), sB_u = smem_u32(sB);

    int tid = threadIdx.x;
    int lane = tid & 31, warp = tid >> 5;
    int wm = warp >> 2, wn = warp & 3;
    int m0 = blockIdx.x * 64, n0 = blockIdx.y * 128;

    float d[2][4][4];
    #pragma unroll
    for (int i = 0; i < 2; i++)
        #pragma unroll
        for (int j = 0; j < 4; j++)
            #pragma unroll
            for (int q = 0; q < 4; q++) d[i][j][q] = 0.f;

    int a_hl[2], a_row[2], a_seg[2];
    #pragma unroll
    for (int i = 0; i < 2; i++) {
        int idx = tid + i * 256;
        a_hl[i] = idx >> 8; int r = idx & 255;
        a_row[i] = r >> 2; a_seg[i] = r & 3;
    }
    int b_hl[4], b_row[4], b_seg[4];
    #pragma unroll
    for (int i = 0; i < 4; i++) {
        int idx = tid + i * 256;
        b_hl[i] = idx >> 9; int r = idx & 511;
        b_row[i] = r >> 2; b_seg[i] = r & 3;
    }

    uint4 rA[2], rB[4];
    #pragma unroll
    for (int i = 0; i < 2; i++) {
        const __nv_bfloat16* src = a_hl[i] ? g_glo : g_ghi;
        rA[i] = *(const uint4*)(src + (size_t)(m0 + a_row[i]) * K5P + a_seg[i] * 8);
    }
    #pragma unroll
    for (int i = 0; i < 4; i++) {
        const __nv_bfloat16* src = b_hl[i] ? g_wlo : g_whi;
        rB[i] = *(const uint4*)(src + (size_t)(n0 + b_row[i]) * K5P + b_seg[i] * 8);
    }
    #pragma unroll
    for (int i = 0; i < 2; i++)
        *(uint4*)(sA + ((a_hl[i]) * 64 + a_row[i]) * GSTR + a_seg[i] * 8) = rA[i];
    #pragma unroll
    for (int i = 0; i < 4; i++)
        *(uint4*)(sB + ((b_hl[i]) * 128 + b_row[i]) * GSTR + b_seg[i] * 8) = rB[i];
    __syncthreads();

    for (int c = 0; c < KCH; c++) {
        int buf = c & 1;
        if (c + 1 < KCH) {
            int kb = (c + 1) * 32;
            #pragma unroll
            for (int i = 0; i < 2; i++) {
                const __nv_bfloat16* src = a_hl[i] ? g_glo : g_ghi;
                rA[i] = *(const uint4*)(src + (size_t)(m0 + a_row[i]) * K5P + kb + a_seg[i] * 8);
            }
            #pragma unroll
            for (int i = 0; i < 4; i++) {
                const __nv_bfloat16* src = b_hl[i] ? g_wlo : g_whi;
                rB[i] = *(const uint4*)(src + (size_t)(n0 + b_row[i]) * K5P + kb + b_seg[i] * 8);
            }
        }
        #pragma unroll
        for (int kk = 0; kk < 2; kk++) {
            unsigned a[2][2][4], bf[2][4][2];
            int arow = lane & 15;
            int acol = kk * 16 + ((lane >> 4) << 3);
            #pragma unroll
            for (int hl = 0; hl < 2; hl++)
                #pragma unroll
                for (int mi = 0; mi < 2; mi++) {
                    unsigned ad = sA_u +
                        (((buf * 2 + hl) * 64 + wm * 32 + mi * 16 + arow) * GSTR + acol) * 2;
                    ldm_x4(ad, a[hl][mi][0], a[hl][mi][1], a[hl][mi][2], a[hl][mi][3]);
                }
            int bn = (lane & 7) + ((lane >> 4) & 1) * 8;
            int bk = kk * 16 + (lane & 8);
            #pragma unroll
            for (int hl = 0; hl < 2; hl++)
                #pragma unroll
                for (int ni = 0; ni < 2; ni++) {
                    unsigned r0, r1, r2, r3;
                    unsigned ad = sB_u +
                        (((buf * 2 + hl) * 128 + wn * 32 + ni * 16 + bn) * GSTR + bk) * 2;
                    ldm_x4(ad, r0, r1, r2, r3);
                    bf[hl][2 * ni][0] = r0;     bf[hl][2 * ni][1] = r1;
                    bf[hl][2 * ni + 1][0] = r2; bf[hl][2 * ni + 1][1] = r3;
                }
            #pragma unroll
            for (int mi = 0; mi < 2; mi++)
                #pragma unroll
                for (int j = 0; j < 4; j++) {
                    mma_bf16(d[mi][j], a[0][mi], bf[0][j]);
                    mma_bf16(d[mi][j], a[0][mi], bf[1][j]);
                    mma_bf16(d[mi][j], a[1][mi], bf[0][j]);
                }
        }
        if (c + 1 < KCH) {
            int nb = buf ^ 1;
            #pragma unroll
            for (int i = 0; i < 2; i++)
                *(uint4*)(sA + ((nb * 2 + a_hl[i]) * 64 + a_row[i]) * GSTR + a_seg[i] * 8) = rA[i];
            #pragma unroll
            for (int i = 0; i < 4; i++)
                *(uint4*)(sB + ((nb * 2 + b_hl[i]) * 128 + b_row[i]) * GSTR + b_seg[i] * 8) = rB[i];
        }
        __syncthreads();
    }

    #pragma unroll
    for (int mi = 0; mi < 2; mi++)
        #pragma unroll
        for (int j = 0; j < 4; j++) {
            int row0 = m0 + wm * 32 + mi * 16 + (lane >> 2);
            int col = n0 + wn * 32 + j * 8 + (lane & 3) * 2;
            float bia = bih0[col], bib = bih0[col + 1];
            if (row0 < SB) {
                g_gi0[(size_t)row0 * G3 + col]     = d[mi][j][0] + bia;
                g_gi0[(size_t)row0 * G3 + col + 1] = d[mi][j][1] + bib;
            }
            if (row0 + 8 < SB) {
                g_gi0[(size_t)(row0 + 8) * G3 + col]     = d[mi][j][2] + bia;
                g_gi0[(size_t)(row0 + 8) * G3 + col + 1] = d[mi][j][3] + bib;
            }
        }
}

// ---------------- persistent GRU ----------------
#define HP 514
#define GRU_SMEM ((48 * 512 + 32 * HP) * 4)

__global__ __launch_bounds__(256, 1) void gru_persist_kernel(
        const float* __restrict__ whh0, const float* __restrict__ bhh0,
        const float* __restrict__ wih1, const float* __restrict__ bih1,
        const float* __restrict__ whh1, const float* __restrict__ bhh1,
        float* __restrict__ d_out) {
    extern __shared__ float sm[];
    float* s_w = sm;
    float* s_h = sm + 48 * 512;
    int tid = threadIdx.x;
    int role = blockIdx.x >> 5;
    int c = blockIdx.x & 31;

    const float* wsrc = (role == 0) ? whh0 : ((role == 1) ? wih1 : whh1);
    for (int e = tid; e < 48 * 512; e += 256) {
        int r = e >> 9, k = e & 511;
        int G = (role == 1) ? (c * 48 + r) : ((r >> 4) * HID + c * 16 + (r & 15));
        s_w[e] = wsrc[(size_t)G * HID + k];
    }

    int bg = tid & 15, jl = tid >> 4;
    const ull* w0 = (const ull*)(s_w + (size_t)jl * 512);
    const ull* w1 = (const ull*)(s_w + (size_t)(16 + jl) * 512);
    const ull* w2 = (const ull*)(s_w + (size_t)(32 + jl) * 512);
    const ull* hp0 = (const ull*)(s_h + (size_t)(2 * bg) * HP);
    const ull* hp1 = (const ull*)(s_h + (size_t)(2 * bg + 1) * HP);

    for (int t = 0; t < S; t++) {
        if (tid == 0) {
            if (role == 0) { if (t) spin32(&g_f0[t - 1]); }
            else if (role == 1) { spin32(&g_f0[t]); }
            else { spin32(&g_f1[t]); if (t) spin32(&g_f2[t - 1]); }
        }
        __syncthreads();

        const float* hsrc = (role == 0) ? (g_h0s + (size_t)t * BH)
                          : (role == 1) ? (g_h0s + (size_t)(t + 1) * BH)
                                        : (g_h1s + (size_t)t * BH);
        for (int e = tid; e < 32 * 128; e += 256) {
            int b = e >> 7, k4 = (e & 127) * 4;
            float4 v = *(const float4*)(hsrc + (size_t)b * HID + k4);
            float* dst = s_h + (size_t)b * HP + k4;
            dst[0] = v.x; dst[1] = v.y; dst[2] = v.z; dst[3] = v.w;
        }
        __syncthreads();

        ull a00 = 0, a01 = 0, a10 = 0, a11 = 0, a20 = 0, a21 = 0;
        #pragma unroll 4
        for (int q = 0; q < 256; q++) {
            ull h0 = hp0[q], h1 = hp1[q];
            ull v0 = w0[q], v1 = w1[q], v2 = w2[q];
            FFMA2(a00, h0, v0); FFMA2(a01, h1, v0);
            FFMA2(a10, h0, v1); FFMA2(a11, h1, v1);
            FFMA2(a20, h0, v2); FFMA2(a21, h1, v2);
        }

        if (role == 1) {
            float* gi = g_gi1 + (size_t)t * BATCH * G3;
            int r0 = c * 48 + jl, r1 = r0 + 16, r2 = r0 + 32;
            int b0 = 2 * bg, b1 = b0 + 1;
            gi[(size_t)b0 * G3 + r0] = hsum2(a00) + bih1[r0];
            gi[(size_t)b1 * G3 + r0] = hsum2(a01) + bih1[r0];
            gi[(size_t)b0 * G3 + r1] = hsum2(a10) + bih1[r1];
            gi[(size_t)b1 * G3 + r1] = hsum2(a11) + bih1[r1];
            gi[(size_t)b0 * G3 + r2] = hsum2(a20) + bih1[r2];
            gi[(size_t)b1 * G3 + r2] = hsum2(a21) + bih1[r2];
        } else {
            int j = c * 16 + jl;
            const float* bhh = (role == 0) ? bhh0 : bhh1;
            const float* gi = ((role == 0) ? g_gi0 : g_gi1) + (size_t)t * BATCH * G3;
            float* hdst = ((role == 0) ? g_h0s : g_h1s) + (size_t)(t + 1) * BH;
            float br = bhh[j], bz = bhh[HID + j], bnn = bhh[2 * HID + j];
            #pragma unroll
            for (int bb = 0; bb < 2; bb++) {
                int b = 2 * bg + bb;
                float ghr = hsum2(bb ? a01 : a00) + br;
                float ghz = hsum2(bb ? a11 : a10) + bz;
                float ghn = hsum2(bb ? a21 : a20) + bnn;
                float gir = gi[(size_t)b * G3 + j];
                float giz = gi[(size_t)b * G3 + HID + j];
                float gin = gi[(size_t)b * G3 + 2 * HID + j];
                float r = 1.f / (1.f + expf(-(gir + ghr)));
                float z = 1.f / (1.f + expf(-(giz + ghz)));
                float n = tanhf(gin + r * ghn);
                float hprev = s_h[(size_t)b * HP + j];
                float hnew = (1.f - z) * n + z * hprev;
                hdst[(size_t)b * HID + j] = hnew;
                if (role == 2) d_out[(size_t)t * BH + b * HID + j] = hnew;
                if (t == S - 1)
                    d_out[(size_t)S * BH + (role == 2 ? BH : 0) + b * HID + j] = hnew;
            }
        }

        __syncthreads();
        if (tid == 0) {
            int* f = (role == 0) ? &g_f0[t] : ((role == 1) ? &g_f1[t] : &g_f2[t]);
            red_release(f);
        }
    }
}

// ---------------- host launch ----------------
extern "C" void kernel_launch(void* const* d_in, const int* in_sizes, int n_in,
                              void* d_out, int out_size) {
    const float* x     = (const float*)d_in[0];
    const int*   ei    = (const int*)d_in[1];
    const float* W1    = (const float*)d_in[2];
    const float* b1    = (const float*)d_in[3];
    const float* W2    = (const float*)d_in[4];
    const float* b2    = (const float*)d_in[5];
    const float* w_ih0 = (const float*)d_in[6];
    const float* w_hh0 = (const float*)d_in[7];
    const float* b_ih0 = (const float*)d_in[8];
    const float* b_hh0 = (const float*)d_in[9];
    const float* w_ih1 = (const float*)d_in[10];
    const float* w_hh1 = (const float*)d_in[11];
    const float* b_ih1 = (const float*)d_in[12];
    const float* b_hh1 = (const float*)d_in[13];
    float* out = (float*)d_out;

    const int SMEM_GEMM = SA_BYTES + SB_BYTES;

    cudaFuncSetAttribute(gcn_kernel, cudaFuncAttributeMaxDynamicSharedMemorySize, SMEM_GCN);
    cudaFuncSetAttribute(gemm_gi0_kernel, cudaFuncAttributeMaxDynamicSharedMemorySize, SMEM_GEMM);
    cudaFuncSetAttribute(gru_persist_kernel, cudaFuncAttributeMaxDynamicSharedMemorySize, GRU_SMEM);

    init_kernel<<<(BH + 255) / 256, 256>>>(ei);
    count_kernel<<<(NEDGE + 255) / 256, 256>>>(ei);
    scan_kernel<<<1, 1024>>>();
    fill_kernel<<<(NEDGE_SL + 255) / 256, 256>>>(ei);
    wconv_kernel<<<(G3 * K5 + 255) / 256, 256>>>(w_ih0);

    gcn_kernel<<<SB / SLC, 1024, SMEM_GCN>>>(x, W1, b1, W2, b2);
    gemm_gi0_kernel<<<dim3(MP / 64, G3 / 128), 256, SMEM_GEMM>>>(b_ih0);

    gru_persist_kernel<<<96, 256, GRU_SMEM>>>(w_hh0, b_hh0, w_ih1, b_ih1,
                                              w_hh1, b_hh1, out);
}

// round 8
// speedup vs baseline: 3.0216x; 1.1544x over previous
#include <cuda_runtime.h>
#include <cuda_bf16.h>
#include <math.h>

#define S      15
#define BATCH  32
#define NNODE  5000
#define NEDGE  80000
#define NEDGE_SL (NEDGE + NNODE)
#define FIN    16
#define HID    512
#define G3     1536
#define SB     (S*BATCH)
#define K5     5000
#define K5P    5056
#define MP     512
#define KCH    158          // 5056 / 32
#define BH     (BATCH*HID)
#define SLC    3

typedef unsigned long long ull;

struct __align__(8) Edge { int s; float w; };

__device__ int   g_indeg[NNODE];
__device__ int   g_off[NNODE + 1];
__device__ int   g_pos[NNODE];
__device__ float g_dinv[NNODE];
__device__ Edge  g_edges[NEDGE_SL];
__device__ int   g_is64;

__device__ __nv_bfloat16 g_ghi[MP * K5P];
__device__ __nv_bfloat16 g_glo[MP * K5P];
__device__ __nv_bfloat16 g_whi[G3 * K5P];
__device__ __nv_bfloat16 g_wlo[G3 * K5P];

__device__ float g_gi0[SB * G3];
__device__ float g_gi1[S * BATCH * G3];
__device__ float g_h0s[(S + 1) * BH];
__device__ float g_h1s[(S + 1) * BH];
__device__ int   g_f0[S], g_f1[S], g_f2[S];

#define FFMA2(c, a, b) asm("fma.rn.f32x2 %0, %1, %2, %0;" : "+l"(c) : "l"(a), "l"(b))
__device__ __forceinline__ float hsum2(ull v) {
    float lo, hi;
    asm("mov.b64 {%0,%1}, %2;" : "=f"(lo), "=f"(hi) : "l"(v));
    return lo + hi;
}
__device__ __forceinline__ unsigned smem_u32(const void* p) {
    return (unsigned)__cvta_generic_to_shared(p);
}
__device__ __forceinline__ void ldm_x4(unsigned a, unsigned& r0, unsigned& r1,
                                       unsigned& r2, unsigned& r3) {
    asm volatile("ldmatrix.sync.aligned.m8n8.x4.shared.b16 {%0,%1,%2,%3}, [%4];"
                 : "=r"(r0), "=r"(r1), "=r"(r2), "=r"(r3) : "r"(a));
}
__device__ __forceinline__ void mma_bf16(float* d, const unsigned* a, const unsigned* b) {
    asm volatile(
        "mma.sync.aligned.m16n8k16.row.col.f32.bf16.bf16.f32 "
        "{%0,%1,%2,%3}, {%4,%5,%6,%7}, {%8,%9}, {%0,%1,%2,%3};"
        : "+f"(d[0]), "+f"(d[1]), "+f"(d[2]), "+f"(d[3])
        : "r"(a[0]), "r"(a[1]), "r"(a[2]), "r"(a[3]), "r"(b[0]), "r"(b[1]));
}
__device__ __forceinline__ void spin32(const int* p) {
    int v;
    do {
        asm volatile("ld.acquire.gpu.b32 %0, [%1];" : "=r"(v) : "l"(p));
        if (v < 32) __nanosleep(64);
    } while (v < 32);
}
__device__ __forceinline__ void red_release(int* p) {
    asm volatile("red.release.gpu.global.add.s32 [%0], %1;" :: "l"(p), "r"(1) : "memory");
}

// ---------------- prep ----------------
__global__ void init_kernel(const int* __restrict__ ei) {
    int i = blockIdx.x * blockDim.x + threadIdx.x;
    if (i < NNODE) g_indeg[i] = 1;
    if (i < BH) { g_h0s[i] = 0.f; g_h1s[i] = 0.f; }
    if (i < S) { g_f0[i] = 0; g_f1[i] = 0; g_f2[i] = 0; }
    if (i == 0) {
        int f = 1;
        for (int q = 0; q < 64; q++) if (ei[2 * q + 1] != 0) { f = 0; break; }
        g_is64 = f;
    }
}
__global__ void count_kernel(const int* __restrict__ ei) {
    int e = blockIdx.x * blockDim.x + threadIdx.x;
    if (e >= NEDGE) return;
    int t = g_is64 ? ei[2 * (NEDGE + e)] : ei[NEDGE + e];
    atomicAdd(&g_indeg[t], 1);
}
__global__ void scan_kernel() {
    __shared__ int ssum[1024];
    int t = threadIdx.x;
    int vals[5]; int s = 0;
    #pragma unroll
    for (int q = 0; q < 5; q++) {
        int idx = t * 5 + q;
        vals[q] = (idx < NNODE) ? g_indeg[idx] : 0;
        s += vals[q];
    }
    ssum[t] = s;
    __syncthreads();
    for (int off = 1; off < 1024; off <<= 1) {
        int v = (t >= off) ? ssum[t - off] : 0;
        __syncthreads();
        ssum[t] += v;
        __syncthreads();
    }
    int run = ssum[t] - s;
    #pragma unroll
    for (int q = 0; q < 5; q++) {
        int idx = t * 5 + q;
        if (idx < NNODE) {
            g_off[idx] = run; g_pos[idx] = run;
            g_dinv[idx] = rsqrtf((float)vals[q]);
            run += vals[q];
        }
    }
    if (t == 1023) g_off[NNODE] = ssum[1023];
}
__global__ void fill_kernel(const int* __restrict__ ei) {
    int e = blockIdx.x * blockDim.x + threadIdx.x;
    if (e >= NEDGE_SL) return;
    int is64 = g_is64;
    int s, t;
    if (e < NEDGE) {
        s = is64 ? ei[2 * e] : ei[e];
        t = is64 ? ei[2 * (NEDGE + e)] : ei[NEDGE + e];
    } else { s = t = e - NEDGE; }
    int idx = atomicAdd(&g_pos[t], 1);
    Edge E; E.s = s; E.w = g_dinv[s] * g_dinv[t];
    g_edges[idx] = E;
}
__global__ void wconv_kernel(const float* __restrict__ wih0) {
    int i = blockIdx.x * blockDim.x + threadIdx.x;
    if (i >= G3 * K5) return;
    int n = i / K5, k = i - n * K5;
    float v = wih0[i];
    __nv_bfloat16 hi = __float2bfloat16(v);
    g_whi[(size_t)n * K5P + k] = hi;
    g_wlo[(size_t)n * K5P + k] = __float2bfloat16(v - __bfloat162float(hi));
}

// ---------------- fused GCN (unchanged) ----------------
#define SMEM_GCN ((NNODE * 6 + NNODE * 3) * 4)

__global__ __launch_bounds__(1024) void gcn_kernel(const float* __restrict__ x,
                                                   const float* __restrict__ W1,
                                                   const float* __restrict__ b1,
                                                   const float* __restrict__ W2,
                                                   const float* __restrict__ b2) {
    extern __shared__ float sm[];
    float* hA = sm;
    float* h2 = sm + NNODE * 6;
    __shared__ float s_w1[SLC][FIN][2];
    __shared__ float s_b1[SLC][2], s_w2[SLC][2], s_b2[SLC];

    int cta = blockIdx.x, tid = threadIdx.x;

    if (tid < SLC * FIN * 2) {
        int sl = tid / (FIN * 2), rem = tid % (FIN * 2);
        int s = (cta * SLC + sl) >> 5;
        s_w1[sl][rem >> 1][rem & 1] = W1[s * (FIN * 2) + rem];
    }
    if (tid >= 128 && tid < 128 + SLC * 2) {
        int q = tid - 128; int sl = q >> 1, c = q & 1;
        int s = (cta * SLC + sl) >> 5;
        s_b1[sl][c] = b1[s * 2 + c];
        s_w2[sl][c] = W2[s * 2 + c];
    }
    if (tid >= 160 && tid < 160 + SLC) {
        int sl = tid - 160;
        s_b2[sl] = b2[((cta * SLC + sl) >> 5)];
    }
    __syncthreads();

    for (int idx = tid; idx < SLC * NNODE; idx += 1024) {
        int sl = idx / NNODE, n = idx - sl * NNODE;
        const float4* xp = (const float4*)(x + ((size_t)(cta * SLC + sl) * NNODE + n) * FIN);
        float xv[16];
        *(float4*)&xv[0] = xp[0]; *(float4*)&xv[4] = xp[1];
        *(float4*)&xv[8] = xp[2]; *(float4*)&xv[12] = xp[3];
        float a0 = 0.f, a1 = 0.f;
        #pragma unroll
        for (int f = 0; f < FIN; f++) {
            a0 += xv[f] * s_w1[sl][f][0];
            a1 += xv[f] * s_w1[sl][f][1];
        }
        hA[n * 6 + sl * 2]     = a0;
        hA[n * 6 + sl * 2 + 1] = a1;
    }
    __syncthreads();

    int warp = tid >> 5, lane = tid & 31;
    int seg = lane >> 3, sub = lane & 7;

    for (int n0 = warp * 4; n0 < NNODE; n0 += 128) {
        int n = n0 + seg;
        int e0 = g_off[n], e1 = g_off[n + 1];
        float ac0 = 0.f, ac1 = 0.f, ac2 = 0.f, ac3 = 0.f, ac4 = 0.f, ac5 = 0.f;
        for (int e = e0 + sub; e < e1; e += 8) {
            Edge E = g_edges[e];
            const float2* src = (const float2*)(hA + E.s * 6);
            float2 p0 = src[0], p1 = src[1], p2 = src[2];
            ac0 += E.w * p0.x; ac1 += E.w * p0.y;
            ac2 += E.w * p1.x; ac3 += E.w * p1.y;
            ac4 += E.w * p2.x; ac5 += E.w * p2.y;
        }
        #pragma unroll
        for (int m = 4; m >= 1; m >>= 1) {
            ac0 += __shfl_xor_sync(0xFFFFFFFF, ac0, m);
            ac1 += __shfl_xor_sync(0xFFFFFFFF, ac1, m);
            ac2 += __shfl_xor_sync(0xFFFFFFFF, ac2, m);
            ac3 += __shfl_xor_sync(0xFFFFFFFF, ac3, m);
            ac4 += __shfl_xor_sync(0xFFFFFFFF, ac4, m);
            ac5 += __shfl_xor_sync(0xFFFFFFFF, ac5, m);
        }
        if (sub == 0) {
            float r0, r1;
            r0 = fmaxf(ac0 + s_b1[0][0], 0.f); r1 = fmaxf(ac1 + s_b1[0][1], 0.f);
            h2[n * 3 + 0] = r0 * s_w2[0][0] + r1 * s_w2[0][1];
            r0 = fmaxf(ac2 + s_b1[1][0], 0.f); r1 = fmaxf(ac3 + s_b1[1][1], 0.f);
            h2[n * 3 + 1] = r0 * s_w2[1][0] + r1 * s_w2[1][1];
            r0 = fmaxf(ac4 + s_b1[2][0], 0.f); r1 = fmaxf(ac5 + s_b1[2][1], 0.f);
            h2[n * 3 + 2] = r0 * s_w2[2][0] + r1 * s_w2[2][1];
        }
    }
    __syncthreads();

    for (int n0 = warp * 4; n0 < NNODE; n0 += 128) {
        int n = n0 + seg;
        int e0 = g_off[n], e1 = g_off[n + 1];
        float a0 = 0.f, a1 = 0.f, a2 = 0.f;
        for (int e = e0 + sub; e < e1; e += 8) {
            Edge E = g_edges[e];
            const float* src = h2 + E.s * 3;
            a0 += E.w * src[0];
            a1 += E.w * src[1];
            a2 += E.w * src[2];
        }
        #pragma unroll
        for (int m = 4; m >= 1; m >>= 1) {
            a0 += __shfl_xor_sync(0xFFFFFFFF, a0, m);
            a1 += __shfl_xor_sync(0xFFFFFFFF, a1, m);
            a2 += __shfl_xor_sync(0xFFFFFFFF, a2, m);
        }
        if (sub == 0) {
            float gv[3] = { tanhf(a0 + s_b2[0]), tanhf(a1 + s_b2[1]), tanhf(a2 + s_b2[2]) };
            #pragma unroll
            for (int sl = 0; sl < SLC; sl++) {
                int sb = cta * SLC + sl;
                __nv_bfloat16 hi = __float2bfloat16(gv[sl]);
                g_ghi[(size_t)sb * K5P + n] = hi;
                g_glo[(size_t)sb * K5P + n] = __float2bfloat16(gv[sl] - __bfloat162float(hi));
            }
        }
    }
}

// ---------------- gi0 GEMM: bf16 split mma.sync, BM=BN=64, 192 CTAs, occ 2 ----------------
#define GSTR 72
#define SAB  36864   // [2buf][2hl][64][72] bf16

__global__ __launch_bounds__(256, 2) void gemm_gi0_kernel(const float* __restrict__ bih0) {
    extern __shared__ char smraw[];
    __nv_bfloat16* sA = (__nv_bfloat16*)smraw;
    __nv_bfloat16* sB = (__nv_bfloat16*)(smraw + SAB);
    unsigned sA_u = smem_u32(sA), sB_u = smem_u32(sB);

    int tid = threadIdx.x;
    int lane = tid & 31, warp = tid >> 5;
    int wm = warp >> 2, wn = warp & 3;
    int m0 = blockIdx.x * 64, n0 = blockIdx.y * 64;

    float d[2][2][4];
    #pragma unroll
    for (int i = 0; i < 2; i++)
        #pragma unroll
        for (int j = 0; j < 2; j++)
            #pragma unroll
            for (int q = 0; q < 4; q++) d[i][j][q] = 0.f;

    int hl_[2], row_[2], seg_[2];
    #pragma unroll
    for (int i = 0; i < 2; i++) {
        int idx = tid + i * 256;
        hl_[i] = idx >> 8; int r = idx & 255;
        row_[i] = r >> 2; seg_[i] = r & 3;
    }

    uint4 rA[2], rB[2];
    #pragma unroll
    for (int i = 0; i < 2; i++) {
        const __nv_bfloat16* sa = hl_[i] ? g_glo : g_ghi;
        const __nv_bfloat16* sb = hl_[i] ? g_wlo : g_whi;
        rA[i] = *(const uint4*)(sa + (size_t)(m0 + row_[i]) * K5P + seg_[i] * 8);
        rB[i] = *(const uint4*)(sb + (size_t)(n0 + row_[i]) * K5P + seg_[i] * 8);
    }
    #pragma unroll
    for (int i = 0; i < 2; i++) {
        *(uint4*)(sA + ((hl_[i]) * 64 + row_[i]) * GSTR + seg_[i] * 8) = rA[i];
        *(uint4*)(sB + ((hl_[i]) * 64 + row_[i]) * GSTR + seg_[i] * 8) = rB[i];
    }
    __syncthreads();

    for (int c = 0; c < KCH; c++) {
        int buf = c & 1;
        if (c + 1 < KCH) {
            int kb = (c + 1) * 32;
            #pragma unroll
            for (int i = 0; i < 2; i++) {
                const __nv_bfloat16* sa = hl_[i] ? g_glo : g_ghi;
                const __nv_bfloat16* sb = hl_[i] ? g_wlo : g_whi;
                rA[i] = *(const uint4*)(sa + (size_t)(m0 + row_[i]) * K5P + kb + seg_[i] * 8);
                rB[i] = *(const uint4*)(sb + (size_t)(n0 + row_[i]) * K5P + kb + seg_[i] * 8);
            }
        }
        #pragma unroll
        for (int kk = 0; kk < 2; kk++) {
            unsigned a[2][2][4], bf[2][2][2];
            int arow = lane & 15;
            int acol = kk * 16 + ((lane >> 4) << 3);
            #pragma unroll
            for (int hl = 0; hl < 2; hl++)
                #pragma unroll
                for (int mi = 0; mi < 2; mi++) {
                    unsigned ad = sA_u +
                        (((buf * 2 + hl) * 64 + wm * 32 + mi * 16 + arow) * GSTR + acol) * 2;
                    ldm_x4(ad, a[hl][mi][0], a[hl][mi][1], a[hl][mi][2], a[hl][mi][3]);
                }
            int bn = (lane & 7) + ((lane >> 4) & 1) * 8;
            int bk = kk * 16 + (lane & 8);
            #pragma unroll
            for (int hl = 0; hl < 2; hl++) {
                unsigned r0, r1, r2, r3;
                unsigned ad = sB_u +
                    (((buf * 2 + hl) * 64 + wn * 16 + bn) * GSTR + bk) * 2;
                ldm_x4(ad, r0, r1, r2, r3);
                bf[hl][0][0] = r0; bf[hl][0][1] = r1;
                bf[hl][1][0] = r2; bf[hl][1][1] = r3;
            }
            #pragma unroll
            for (int mi = 0; mi < 2; mi++)
                #pragma unroll
                for (int j = 0; j < 2; j++) {
                    mma_bf16(d[mi][j], a[0][mi], bf[0][j]);
                    mma_bf16(d[mi][j], a[0][mi], bf[1][j]);
                    mma_bf16(d[mi][j], a[1][mi], bf[0][j]);
                }
        }
        if (c + 1 < KCH) {
            int nb = buf ^ 1;
            #pragma unroll
            for (int i = 0; i < 2; i++) {
                *(uint4*)(sA + ((nb * 2 + hl_[i]) * 64 + row_[i]) * GSTR + seg_[i] * 8) = rA[i];
                *(uint4*)(sB + ((nb * 2 + hl_[i]) * 64 + row_[i]) * GSTR + seg_[i] * 8) = rB[i];
            }
        }
        __syncthreads();
    }

    #pragma unroll
    for (int mi = 0; mi < 2; mi++)
        #pragma unroll
        for (int j = 0; j < 2; j++) {
            int row0 = m0 + wm * 32 + mi * 16 + (lane >> 2);
            int col = n0 + wn * 16 + j * 8 + (lane & 3) * 2;
            float bia = bih0[col], bib = bih0[col + 1];
            if (row0 < SB) {
                g_gi0[(size_t)row0 * G3 + col]     = d[mi][j][0] + bia;
                g_gi0[(size_t)row0 * G3 + col + 1] = d[mi][j][1] + bib;
            }
            if (row0 + 8 < SB) {
                g_gi0[(size_t)(row0 + 8) * G3 + col]     = d[mi][j][2] + bia;
                g_gi0[(size_t)(row0 + 8) * G3 + col + 1] = d[mi][j][3] + bib;
            }
        }
}

// ---------------- persistent GRU: 4 batches/thread, k-split x2, conflict-free banks ----------------
#define WPS 552          // w row stride (floats), k-hole at 272:  8 mod 32
#define HPX 546          // h row stride (floats), k-hole at 272:  2 mod 32
#define GRU_SMEM ((48 * WPS + 32 * HPX) * 4)

__global__ __launch_bounds__(256, 1) void gru_persist_kernel(
        const float* __restrict__ whh0, const float* __restrict__ bhh0,
        const float* __restrict__ wih1, const float* __restrict__ bih1,
        const float* __restrict__ whh1, const float* __restrict__ bhh1,
        float* __restrict__ d_out) {
    extern __shared__ float sm[];
    float* s_w = sm;
    float* s_h = sm + 48 * WPS;
    int tid = threadIdx.x;
    int role = blockIdx.x >> 5;
    int c = blockIdx.x & 31;

    const float* wsrc = (role == 0) ? whh0 : ((role == 1) ? wih1 : whh1);
    for (int e = tid; e < 48 * 512; e += 256) {
        int r = e >> 9, k = e & 511;
        int G = (role == 1) ? (c * 48 + r) : ((r >> 4) * HID + c * 16 + (r & 15));
        s_w[r * WPS + (k < 256 ? k : k + 16)] = wsrc[(size_t)G * HID + k];
    }

    int jl = tid >> 4, r4 = tid & 15, ks = r4 >> 3, bg = r4 & 7;
    const ull* wp0 = (const ull*)(s_w + (0 * 16 + jl) * WPS + ks * 272);
    const ull* wp1 = (const ull*)(s_w + (1 * 16 + jl) * WPS + ks * 272);
    const ull* wp2 = (const ull*)(s_w + (2 * 16 + jl) * WPS + ks * 272);
    const ull* hp0 = (const ull*)(s_h + (bg + 0)  * HPX + ks * 272);
    const ull* hp1 = (const ull*)(s_h + (bg + 8)  * HPX + ks * 272);
    const ull* hp2 = (const ull*)(s_h + (bg + 16) * HPX + ks * 272);
    const ull* hp3 = (const ull*)(s_h + (bg + 24) * HPX + ks * 272);

    for (int t = 0; t < S; t++) {
        if (tid == 0) {
            if (role == 0) { if (t) spin32(&g_f0[t - 1]); }
            else if (role == 1) { spin32(&g_f0[t]); }
            else { spin32(&g_f1[t]); if (t) spin32(&g_f2[t - 1]); }
        }
        __syncthreads();

        const float* hsrc = (role == 0) ? (g_h0s + (size_t)t * BH)
                          : (role == 1) ? (g_h0s + (size_t)(t + 1) * BH)
                                        : (g_h1s + (size_t)t * BH);
        for (int e = tid; e < 32 * 128; e += 256) {
            int b = e >> 7, k4 = (e & 127) * 4;
            float4 v = *(const float4*)(hsrc + (size_t)b * HID + k4);
            float* dst = s_h + b * HPX + (k4 < 256 ? k4 : k4 + 16);
            *(float2*)dst = make_float2(v.x, v.y);
            *(float2*)(dst + 2) = make_float2(v.z, v.w);
        }
        __syncthreads();

        ull a[3][4];
        #pragma unroll
        for (int g = 0; g < 3; g++)
            #pragma unroll
            for (int i = 0; i < 4; i++) a[g][i] = 0ull;

        #pragma unroll 4
        for (int q = 0; q < 128; q++) {
            ull h0 = hp0[q], h1 = hp1[q], h2 = hp2[q], h3 = hp3[q];
            ull v0 = wp0[q], v1 = wp1[q], v2 = wp2[q];
            FFMA2(a[0][0], h0, v0); FFMA2(a[0][1], h1, v0);
            FFMA2(a[0][2], h2, v0); FFMA2(a[0][3], h3, v0);
            FFMA2(a[1][0], h0, v1); FFMA2(a[1][1], h1, v1);
            FFMA2(a[1][2], h2, v1); FFMA2(a[1][3], h3, v1);
            FFMA2(a[2][0], h0, v2); FFMA2(a[2][1], h1, v2);
            FFMA2(a[2][2], h2, v2); FFMA2(a[2][3], h3, v2);
        }

        float sv[3][4];
        #pragma unroll
        for (int g = 0; g < 3; g++)
            #pragma unroll
            for (int i = 0; i < 4; i++) {
                float v = hsum2(a[g][i]);
                sv[g][i] = v + __shfl_xor_sync(0xFFFFFFFF, v, 8);
            }

        if (role == 1) {
            float* gi = g_gi1 + (size_t)t * BATCH * G3;
            int r0 = c * 48 + jl, r1 = r0 + 16, r2 = r0 + 32;
            float b0 = bih1[r0], b1v = bih1[r1], b2v = bih1[r2];
            #pragma unroll
            for (int bb = 0; bb < 2; bb++) {
                int i = 2 * ks + bb;
                int b = bg + 8 * i;
                gi[(size_t)b * G3 + r0] = sv[0][i] + b0;
                gi[(size_t)b * G3 + r1] = sv[1][i] + b1v;
                gi[(size_t)b * G3 + r2] = sv[2][i] + b2v;
            }
        } else {
            int j = c * 16 + jl;
            const float* bhh = (role == 0) ? bhh0 : bhh1;
            const float* gi = ((role == 0) ? g_gi0 : g_gi1) + (size_t)t * BATCH * G3;
            float* hdst = ((role == 0) ? g_h0s : g_h1s) + (size_t)(t + 1) * BH;
            float br = bhh[j], bz = bhh[HID + j], bnn = bhh[2 * HID + j];
            int joff = (j < 256 ? j : j + 16);
            #pragma unroll
            for (int bb = 0; bb < 2; bb++) {
                int i = 2 * ks + bb;
                int b = bg + 8 * i;
                float ghr = sv[0][i] + br;
                float ghz = sv[1][i] + bz;
                float ghn = sv[2][i] + bnn;
                float gir = gi[(size_t)b * G3 + j];
                float giz = gi[(size_t)b * G3 + HID + j];
                float gin = gi[(size_t)b * G3 + 2 * HID + j];
                float r = 1.f / (1.f + expf(-(gir + ghr)));
                float z = 1.f / (1.f + expf(-(giz + ghz)));
                float n = tanhf(gin + r * ghn);
                float hprev = s_h[b * HPX + joff];
                float hnew = (1.f - z) * n + z * hprev;
                hdst[(size_t)b * HID + j] = hnew;
                if (role == 2) d_out[(size_t)t * BH + b * HID + j] = hnew;
                if (t == S - 1)
                    d_out[(size_t)S * BH + (role == 2 ? BH : 0) + b * HID + j] = hnew;
            }
        }

        __syncthreads();
        if (tid == 0) {
            int* f = (role == 0) ? &g_f0[t] : ((role == 1) ? &g_f1[t] : &g_f2[t]);
            red_release(f);
        }
    }
}

// ---------------- host launch ----------------
extern "C" void kernel_launch(void* const* d_in, const int* in_sizes, int n_in,
                              void* d_out, int out_size) {
    const float* x     = (const float*)d_in[0];
    const int*   ei    = (const int*)d_in[1];
    const float* W1    = (const float*)d_in[2];
    const float* b1    = (const float*)d_in[3];
    const float* W2    = (const float*)d_in[4];
    const float* b2    = (const float*)d_in[5];
    const float* w_ih0 = (const float*)d_in[6];
    const float* w_hh0 = (const float*)d_in[7];
    const float* b_ih0 = (const float*)d_in[8];
    const float* b_hh0 = (const float*)d_in[9];
    const float* w_ih1 = (const float*)d_in[10];
    const float* w_hh1 = (const float*)d_in[11];
    const float* b_ih1 = (const float*)d_in[12];
    const float* b_hh1 = (const float*)d_in[13];
    float* out = (float*)d_out;

    const int SMEM_GEMM = 2 * SAB;

    cudaFuncSetAttribute(gcn_kernel, cudaFuncAttributeMaxDynamicSharedMemorySize, SMEM_GCN);
    cudaFuncSetAttribute(gemm_gi0_kernel, cudaFuncAttributeMaxDynamicSharedMemorySize, SMEM_GEMM);
    cudaFuncSetAttribute(gru_persist_kernel, cudaFuncAttributeMaxDynamicSharedMemorySize, GRU_SMEM);

    init_kernel<<<(BH + 255) / 256, 256>>>(ei);
    count_kernel<<<(NEDGE + 255) / 256, 256>>>(ei);
    scan_kernel<<<1, 1024>>>();
    fill_kernel<<<(NEDGE_SL + 255) / 256, 256>>>(ei);
    wconv_kernel<<<(G3 * K5 + 255) / 256, 256>>>(w_ih0);

    gcn_kernel<<<SB / SLC, 1024, SMEM_GCN>>>(x, W1, b1, W2, b2);
    gemm_gi0_kernel<<<dim3(MP / 64, G3 / 64), 256, SMEM_GEMM>>>(b_ih0);

    gru_persist_kernel<<<96, 256, GRU_SMEM>>>(w_hh0, b_hh0, w_ih1, b_ih1,
                                              w_hh1, b_hh1, out);
}

// round 9
// speedup vs baseline: 3.2437x; 1.0735x over previous
#include <cuda_runtime.h>
#include <cuda_bf16.h>
#include <math.h>

#define S      15
#define BATCH  32
#define NNODE  5000
#define NEDGE  80000
#define NEDGE_SL (NEDGE + NNODE)
#define FIN    16
#define HID    512
#define G3     1536
#define SB     (S*BATCH)
#define K5     5000
#define K5P    5056
#define MP     512
#define KCH    158
#define BH     (BATCH*HID)
#define SLC    3
#define GCN_CTAS (SB / SLC)      // 160
#define WCONV_CTAS 40

typedef unsigned long long ull;

struct __align__(8) Edge { int s; float w; };

__device__ int   g_indeg[NNODE];
__device__ int   g_off[NNODE + 1];
__device__ int   g_pos[NNODE];
__device__ float g_dinv[NNODE];
__device__ Edge  g_edges[NEDGE_SL];
__device__ int   g_is64;

__device__ __nv_bfloat16 g_ghi[MP * K5P];
__device__ __nv_bfloat16 g_glo[MP * K5P];
__device__ __nv_bfloat16 g_whi[G3 * K5P];
__device__ __nv_bfloat16 g_wlo[G3 * K5P];

__device__ float g_gi0[SB * G3];
__device__ float g_gi1[S * BATCH * G3];
__device__ float g_h0s[(S + 1) * BH];
__device__ float g_h1s[(S + 1) * BH];
__device__ int   g_f0[S], g_f1[S], g_f2[S];

#define FFMA2(c, a, b) asm("fma.rn.f32x2 %0, %1, %2, %0;" : "+l"(c) : "l"(a), "l"(b))
__device__ __forceinline__ float hsum2(ull v) {
    float lo, hi;
    asm("mov.b64 {%0,%1}, %2;" : "=f"(lo), "=f"(hi) : "l"(v));
    return lo + hi;
}
__device__ __forceinline__ unsigned smem_u32(const void* p) {
    return (unsigned)__cvta_generic_to_shared(p);
}
__device__ __forceinline__ void ldm_x4(unsigned a, unsigned& r0, unsigned& r1,
                                       unsigned& r2, unsigned& r3) {
    asm volatile("ldmatrix.sync.aligned.m8n8.x4.shared.b16 {%0,%1,%2,%3}, [%4];"
                 : "=r"(r0), "=r"(r1), "=r"(r2), "=r"(r3) : "r"(a));
}
__device__ __forceinline__ void mma_bf16(float* d, const unsigned* a, const unsigned* b) {
    asm volatile(
        "mma.sync.aligned.m16n8k16.row.col.f32.bf16.bf16.f32 "
        "{%0,%1,%2,%3}, {%4,%5,%6,%7}, {%8,%9}, {%0,%1,%2,%3};"
        : "+f"(d[0]), "+f"(d[1]), "+f"(d[2]), "+f"(d[3])
        : "r"(a[0]), "r"(a[1]), "r"(a[2]), "r"(a[3]), "r"(b[0]), "r"(b[1]));
}
__device__ __forceinline__ void spin32(const int* p) {
    int v;
    do {
        asm volatile("ld.acquire.gpu.b32 %0, [%1];" : "=r"(v) : "l"(p));
        if (v < 32) __nanosleep(64);
    } while (v < 32);
}
__device__ __forceinline__ void red_release(int* p) {
    asm volatile("red.release.gpu.global.add.s32 [%0], %1;" :: "l"(p), "r"(1) : "memory");
}

// ---------------- prep ----------------
__global__ void init_kernel(const int* __restrict__ ei) {
    int i = blockIdx.x * blockDim.x + threadIdx.x;
    if (i < NNODE) g_indeg[i] = 1;
    if (i < BH) { g_h0s[i] = 0.f; g_h1s[i] = 0.f; }
    if (i < S) { g_f0[i] = 0; g_f1[i] = 0; g_f2[i] = 0; }
    if (i == 0) {
        int f = 1;
        for (int q = 0; q < 64; q++) if (ei[2 * q + 1] != 0) { f = 0; break; }
        g_is64 = f;
    }
}
__global__ void count_kernel(const int* __restrict__ ei) {
    int e = blockIdx.x * blockDim.x + threadIdx.x;
    if (e >= NEDGE) return;
    int t = g_is64 ? ei[2 * (NEDGE + e)] : ei[NEDGE + e];
    atomicAdd(&g_indeg[t], 1);
}
__global__ void scan_kernel() {
    __shared__ int ssum[1024];
    int t = threadIdx.x;
    int vals[5]; int s = 0;
    #pragma unroll
    for (int q = 0; q < 5; q++) {
        int idx = t * 5 + q;
        vals[q] = (idx < NNODE) ? g_indeg[idx] : 0;
        s += vals[q];
    }
    ssum[t] = s;
    __syncthreads();
    for (int off = 1; off < 1024; off <<= 1) {
        int v = (t >= off) ? ssum[t - off] : 0;
        __syncthreads();
        ssum[t] += v;
        __syncthreads();
    }
    int run = ssum[t] - s;
    #pragma unroll
    for (int q = 0; q < 5; q++) {
        int idx = t * 5 + q;
        if (idx < NNODE) {
            g_off[idx] = run; g_pos[idx] = run;
            g_dinv[idx] = rsqrtf((float)vals[q]);
            run += vals[q];
        }
    }
    if (t == 1023) g_off[NNODE] = ssum[1023];
}
__global__ void fill_kernel(const int* __restrict__ ei) {
    int e = blockIdx.x * blockDim.x + threadIdx.x;
    if (e >= NEDGE_SL) return;
    int is64 = g_is64;
    int s, t;
    if (e < NEDGE) {
        s = is64 ? ei[2 * e] : ei[e];
        t = is64 ? ei[2 * (NEDGE + e)] : ei[NEDGE + e];
    } else { s = t = e - NEDGE; }
    int idx = atomicAdd(&g_pos[t], 1);
    Edge E; E.s = s; E.w = g_dinv[s] * g_dinv[t];
    g_edges[idx] = E;
}

// ---------------- fused GCN + wconv (extra CTAs) ----------------
#define SMEM_GCN ((NNODE * 6 + NNODE * 3) * 4)

__global__ __launch_bounds__(1024) void gcn_kernel(const float* __restrict__ x,
                                                   const float* __restrict__ W1,
                                                   const float* __restrict__ b1,
                                                   const float* __restrict__ W2,
                                                   const float* __restrict__ b2,
                                                   const float* __restrict__ wih0) {
    int cta = blockIdx.x, tid = threadIdx.x;

    if (cta >= GCN_CTAS) {
        // wconv role: split w_ih0 into bf16 hi/lo
        int base = (cta - GCN_CTAS) * 1024 + tid;
        for (int i = base; i < G3 * K5; i += WCONV_CTAS * 1024) {
            int n = i / K5, k = i - n * K5;
            float v = wih0[i];
            __nv_bfloat16 hi = __float2bfloat16(v);
            g_whi[(size_t)n * K5P + k] = hi;
            g_wlo[(size_t)n * K5P + k] = __float2bfloat16(v - __bfloat162float(hi));
        }
        return;
    }

    extern __shared__ float sm[];
    float* hA = sm;
    float* h2 = sm + NNODE * 6;
    __shared__ float s_w1[SLC][FIN][2];
    __shared__ float s_b1[SLC][2], s_w2[SLC][2], s_b2[SLC];

    if (tid < SLC * FIN * 2) {
        int sl = tid / (FIN * 2), rem = tid % (FIN * 2);
        int s = (cta * SLC + sl) >> 5;
        s_w1[sl][rem >> 1][rem & 1] = W1[s * (FIN * 2) + rem];
    }
    if (tid >= 128 && tid < 128 + SLC * 2) {
        int q = tid - 128; int sl = q >> 1, c = q & 1;
        int s = (cta * SLC + sl) >> 5;
        s_b1[sl][c] = b1[s * 2 + c];
        s_w2[sl][c] = W2[s * 2 + c];
    }
    if (tid >= 160 && tid < 160 + SLC) {
        int sl = tid - 160;
        s_b2[sl] = b2[((cta * SLC + sl) >> 5)];
    }
    __syncthreads();

    for (int idx = tid; idx < SLC * NNODE; idx += 1024) {
        int sl = idx / NNODE, n = idx - sl * NNODE;
        const float4* xp = (const float4*)(x + ((size_t)(cta * SLC + sl) * NNODE + n) * FIN);
        float xv[16];
        *(float4*)&xv[0] = xp[0]; *(float4*)&xv[4] = xp[1];
        *(float4*)&xv[8] = xp[2]; *(float4*)&xv[12] = xp[3];
        float a0 = 0.f, a1 = 0.f;
        #pragma unroll
        for (int f = 0; f < FIN; f++) {
            a0 += xv[f] * s_w1[sl][f][0];
            a1 += xv[f] * s_w1[sl][f][1];
        }
        hA[n * 6 + sl * 2]     = a0;
        hA[n * 6 + sl * 2 + 1] = a1;
    }
    __syncthreads();

    int warp = tid >> 5, lane = tid & 31;
    int seg = lane >> 3, sub = lane & 7;

    for (int n0 = warp * 4; n0 < NNODE; n0 += 128) {
        int n = n0 + seg;
        int e0 = g_off[n], e1 = g_off[n + 1];
        float ac0 = 0.f, ac1 = 0.f, ac2 = 0.f, ac3 = 0.f, ac4 = 0.f, ac5 = 0.f;
        for (int e = e0 + sub; e < e1; e += 8) {
            Edge E = g_edges[e];
            const float2* src = (const float2*)(hA + E.s * 6);
            float2 p0 = src[0], p1 = src[1], p2 = src[2];
            ac0 += E.w * p0.x; ac1 += E.w * p0.y;
            ac2 += E.w * p1.x; ac3 += E.w * p1.y;
            ac4 += E.w * p2.x; ac5 += E.w * p2.y;
        }
        #pragma unroll
        for (int m = 4; m >= 1; m >>= 1) {
            ac0 += __shfl_xor_sync(0xFFFFFFFF, ac0, m);
            ac1 += __shfl_xor_sync(0xFFFFFFFF, ac1, m);
            ac2 += __shfl_xor_sync(0xFFFFFFFF, ac2, m);
            ac3 += __shfl_xor_sync(0xFFFFFFFF, ac3, m);
            ac4 += __shfl_xor_sync(0xFFFFFFFF, ac4, m);
            ac5 += __shfl_xor_sync(0xFFFFFFFF, ac5, m);
        }
        if (sub == 0) {
            float r0, r1;
            r0 = fmaxf(ac0 + s_b1[0][0], 0.f); r1 = fmaxf(ac1 + s_b1[0][1], 0.f);
            h2[n * 3 + 0] = r0 * s_w2[0][0] + r1 * s_w2[0][1];
            r0 = fmaxf(ac2 + s_b1[1][0], 0.f); r1 = fmaxf(ac3 + s_b1[1][1], 0.f);
            h2[n * 3 + 1] = r0 * s_w2[1][0] + r1 * s_w2[1][1];
            r0 = fmaxf(ac4 + s_b1[2][0], 0.f); r1 = fmaxf(ac5 + s_b1[2][1], 0.f);
            h2[n * 3 + 2] = r0 * s_w2[2][0] + r1 * s_w2[2][1];
        }
    }
    __syncthreads();

    // phase 3a: propagate2 raw sums -> hA[n*3+sl]
    for (int n0 = warp * 4; n0 < NNODE; n0 += 128) {
        int n = n0 + seg;
        int e0 = g_off[n], e1 = g_off[n + 1];
        float a0 = 0.f, a1 = 0.f, a2 = 0.f;
        for (int e = e0 + sub; e < e1; e += 8) {
            Edge E = g_edges[e];
            const float* src = h2 + E.s * 3;
            a0 += E.w * src[0];
            a1 += E.w * src[1];
            a2 += E.w * src[2];
        }
        #pragma unroll
        for (int m = 4; m >= 1; m >>= 1) {
            a0 += __shfl_xor_sync(0xFFFFFFFF, a0, m);
            a1 += __shfl_xor_sync(0xFFFFFFFF, a1, m);
            a2 += __shfl_xor_sync(0xFFFFFFFF, a2, m);
        }
        if (sub == 0) {
            hA[n * 3 + 0] = a0;
            hA[n * 3 + 1] = a1;
            hA[n * 3 + 2] = a2;
        }
    }
    __syncthreads();

    // phase 3b: dense bias + tanh + bf16 hi/lo split (all lanes active)
    for (int n = tid; n < NNODE; n += 1024) {
        #pragma unroll
        for (int sl = 0; sl < SLC; sl++) {
            float g = tanhf(hA[n * 3 + sl] + s_b2[sl]);
            int sb = cta * SLC + sl;
            __nv_bfloat16 hi = __float2bfloat16(g);
            g_ghi[(size_t)sb * K5P + n] = hi;
            g_glo[(size_t)sb * K5P + n] = __float2bfloat16(g - __bfloat162float(hi));
        }
    }
}

// ---------------- gi0 GEMM: bf16 split mma.sync, BM=BN=64, 192 CTAs, occ 2 (R8 winner) ----------------
#define GSTR 72
#define SAB  36864

__global__ __launch_bounds__(256, 2) void gemm_gi0_kernel(const float* __restrict__ bih0) {
    extern __shared__ char smraw[];
    __nv_bfloat16* sA = (__nv_bfloat16*)smraw;
    __nv_bfloat16* sB = (__nv_bfloat16*)(smraw + SAB);
    unsigned sA_u = smem_u32(sA), sB_u = smem_u32(sB);

    int tid = threadIdx.x;
    int lane = tid & 31, warp = tid >> 5;
    int wm = warp >> 2, wn = warp & 3;
    int m0 = blockIdx.x * 64, n0 = blockIdx.y * 64;

    float d[2][2][4];
    #pragma unroll
    for (int i = 0; i < 2; i++)
        #pragma unroll
        for (int j = 0; j < 2; j++)
            #pragma unroll
            for (int q = 0; q < 4; q++) d[i][j][q] = 0.f;

    int hl_[2], row_[2], seg_[2];
    #pragma unroll
    for (int i = 0; i < 2; i++) {
        int idx = tid + i * 256;
        hl_[i] = idx >> 8; int r = idx & 255;
        row_[i] = r >> 2; seg_[i] = r & 3;
    }

    uint4 rA[2], rB[2];
    #pragma unroll
    for (int i = 0; i < 2; i++) {
        const __nv_bfloat16* sa = hl_[i] ? g_glo : g_ghi;
        const __nv_bfloat16* sb = hl_[i] ? g_wlo : g_whi;
        rA[i] = *(const uint4*)(sa + (size_t)(m0 + row_[i]) * K5P + seg_[i] * 8);
        rB[i] = *(const uint4*)(sb + (size_t)(n0 + row_[i]) * K5P + seg_[i] * 8);
    }
    #pragma unroll
    for (int i = 0; i < 2; i++) {
        *(uint4*)(sA + ((hl_[i]) * 64 + row_[i]) * GSTR + seg_[i] * 8) = rA[i];
        *(uint4*)(sB + ((hl_[i]) * 64 + row_[i]) * GSTR + seg_[i] * 8) = rB[i];
    }
    __syncthreads();

    for (int c = 0; c < KCH; c++) {
        int buf = c & 1;
        if (c + 1 < KCH) {
            int kb = (c + 1) * 32;
            #pragma unroll
            for (int i = 0; i < 2; i++) {
                const __nv_bfloat16* sa = hl_[i] ? g_glo : g_ghi;
                const __nv_bfloat16* sb = hl_[i] ? g_wlo : g_whi;
                rA[i] = *(const uint4*)(sa + (size_t)(m0 + row_[i]) * K5P + kb + seg_[i] * 8);
                rB[i] = *(const uint4*)(sb + (size_t)(n0 + row_[i]) * K5P + kb + seg_[i] * 8);
            }
        }
        #pragma unroll
        for (int kk = 0; kk < 2; kk++) {
            unsigned a[2][2][4], bf[2][2][2];
            int arow = lane & 15;
            int acol = kk * 16 + ((lane >> 4) << 3);
            #pragma unroll
            for (int hl = 0; hl < 2; hl++)
                #pragma unroll
                for (int mi = 0; mi < 2; mi++) {
                    unsigned ad = sA_u +
                        (((buf * 2 + hl) * 64 + wm * 32 + mi * 16 + arow) * GSTR + acol) * 2;
                    ldm_x4(ad, a[hl][mi][0], a[hl][mi][1], a[hl][mi][2], a[hl][mi][3]);
                }
            int bn = (lane & 7) + ((lane >> 4) & 1) * 8;
            int bk = kk * 16 + (lane & 8);
            #pragma unroll
            for (int hl = 0; hl < 2; hl++) {
                unsigned r0, r1, r2, r3;
                unsigned ad = sB_u +
                    (((buf * 2 + hl) * 64 + wn * 16 + bn) * GSTR + bk) * 2;
                ldm_x4(ad, r0, r1, r2, r3);
                bf[hl][0][0] = r0; bf[hl][0][1] = r1;
                bf[hl][1][0] = r2; bf[hl][1][1] = r3;
            }
            #pragma unroll
            for (int mi = 0; mi < 2; mi++)
                #pragma unroll
                for (int j = 0; j < 2; j++) {
                    mma_bf16(d[mi][j], a[0][mi], bf[0][j]);
                    mma_bf16(d[mi][j], a[0][mi], bf[1][j]);
                    mma_bf16(d[mi][j], a[1][mi], bf[0][j]);
                }
        }
        if (c + 1 < KCH) {
            int nb = buf ^ 1;
            #pragma unroll
            for (int i = 0; i < 2; i++) {
                *(uint4*)(sA + ((nb * 2 + hl_[i]) * 64 + row_[i]) * GSTR + seg_[i] * 8) = rA[i];
                *(uint4*)(sB + ((nb * 2 + hl_[i]) * 64 + row_[i]) * GSTR + seg_[i] * 8) = rB[i];
            }
        }
        __syncthreads();
    }

    #pragma unroll
    for (int mi = 0; mi < 2; mi++)
        #pragma unroll
        for (int j = 0; j < 2; j++) {
            int row0 = m0 + wm * 32 + mi * 16 + (lane >> 2);
            int col = n0 + wn * 16 + j * 8 + (lane & 3) * 2;
            float bia = bih0[col], bib = bih0[col + 1];
            if (row0 < SB) {
                g_gi0[(size_t)row0 * G3 + col]     = d[mi][j][0] + bia;
                g_gi0[(size_t)row0 * G3 + col + 1] = d[mi][j][1] + bib;
            }
            if (row0 + 8 < SB) {
                g_gi0[(size_t)(row0 + 8) * G3 + col]     = d[mi][j][2] + bia;
                g_gi0[(size_t)(row0 + 8) * G3 + col + 1] = d[mi][j][3] + bib;
            }
        }
}

// ---------------- persistent GRU: 8 batches/thread, k-split x4, bank-holed smem ----------------
#define KSEG 136
#define HPX  546
#define WPS  548
#define GRU_SMEM ((48 * WPS + 32 * HPX) * 4)

__global__ __launch_bounds__(256, 1) void gru_persist_kernel(
        const float* __restrict__ whh0, const float* __restrict__ bhh0,
        const float* __restrict__ wih1, const float* __restrict__ bih1,
        const float* __restrict__ whh1, const float* __restrict__ bhh1,
        float* __restrict__ d_out) {
    extern __shared__ float sm[];
    float* s_w = sm;
    float* s_h = sm + 48 * WPS;
    int tid = threadIdx.x;
    int role = blockIdx.x >> 5;
    int c = blockIdx.x & 31;

    const float* wsrc = (role == 0) ? whh0 : ((role == 1) ? wih1 : whh1);
    for (int e = tid; e < 48 * 512; e += 256) {
        int r = e >> 9, k = e & 511;
        int G = (role == 1) ? (c * 48 + r) : ((r >> 4) * HID + c * 16 + (r & 15));
        s_w[r * WPS + (k >> 7) * KSEG + (k & 127)] = wsrc[(size_t)G * HID + k];
    }

    int jl = tid >> 4, r4 = tid & 15, ks = r4 >> 2, bg = r4 & 3;
    const ull* wp0 = (const ull*)(s_w + (0 * 16 + jl) * WPS + ks * KSEG);
    const ull* wp1 = (const ull*)(s_w + (1 * 16 + jl) * WPS + ks * KSEG);
    const ull* wp2 = (const ull*)(s_w + (2 * 16 + jl) * WPS + ks * KSEG);
    const ull* hp[8];
    #pragma unroll
    for (int i = 0; i < 8; i++)
        hp[i] = (const ull*)(s_h + (bg + 4 * i) * HPX + ks * KSEG);

    for (int t = 0; t < S; t++) {
        if (tid == 0) {
            if (role == 0) { if (t) spin32(&g_f0[t - 1]); }
            else if (role == 1) { spin32(&g_f0[t]); }
            else { spin32(&g_f1[t]); if (t) spin32(&g_f2[t - 1]); }
        }
        __syncthreads();

        const float* hsrc = (role == 0) ? (g_h0s + (size_t)t * BH)
                          : (role == 1) ? (g_h0s + (size_t)(t + 1) * BH)
                                        : (g_h1s + (size_t)t * BH);
        for (int e = tid; e < 32 * 128; e += 256) {
            int b = e >> 7, k4 = (e & 127) * 4;
            float4 v = *(const float4*)(hsrc + (size_t)b * HID + k4);
            float* dst = s_h + b * HPX + (k4 >> 7) * KSEG + (k4 & 127);
            *(float2*)dst = make_float2(v.x, v.y);
            *(float2*)(dst + 2) = make_float2(v.z, v.w);
        }
        __syncthreads();

        ull a0[8], a1[8], a2[8];
        #pragma unroll
        for (int i = 0; i < 8; i++) { a0[i] = 0ull; a1[i] = 0ull; a2[i] = 0ull; }

        #pragma unroll 2
        for (int q = 0; q < 64; q++) {
            ull v0 = wp0[q], v1 = wp1[q], v2 = wp2[q];
            #pragma unroll
            for (int i = 0; i < 8; i++) {
                ull h = hp[i][q];
                FFMA2(a0[i], h, v0);
                FFMA2(a1[i], h, v1);
                FFMA2(a2[i], h, v2);
            }
        }

        float sv0[8], sv1[8], sv2[8];
        #pragma unroll
        for (int i = 0; i < 8; i++) {
            float v;
            v = hsum2(a0[i]);
            v += __shfl_xor_sync(0xFFFFFFFF, v, 4);
            v += __shfl_xor_sync(0xFFFFFFFF, v, 8);
            sv0[i] = v;
            v = hsum2(a1[i]);
            v += __shfl_xor_sync(0xFFFFFFFF, v, 4);
            v += __shfl_xor_sync(0xFFFFFFFF, v, 8);
            sv1[i] = v;
            v = hsum2(a2[i]);
            v += __shfl_xor_sync(0xFFFFFFFF, v, 4);
            v += __shfl_xor_sync(0xFFFFFFFF, v, 8);
            sv2[i] = v;
        }

        if (role == 1) {
            float* gi = g_gi1 + (size_t)t * BATCH * G3;
            int r0 = c * 48 + jl, r1 = r0 + 16, r2 = r0 + 32;
            float b0 = bih1[r0], b1v = bih1[r1], b2v = bih1[r2];
            #pragma unroll
            for (int bb = 0; bb < 2; bb++) {
                int i = 2 * ks + bb;
                int b = bg + 4 * i;
                gi[(size_t)b * G3 + r0] = sv0[i] + b0;
                gi[(size_t)b * G3 + r1] = sv1[i] + b1v;
                gi[(size_t)b * G3 + r2] = sv2[i] + b2v;
            }
        } else {
            int j = c * 16 + jl;
            const float* bhh = (role == 0) ? bhh0 : bhh1;
            const float* gi = ((role == 0) ? g_gi0 : g_gi1) + (size_t)t * BATCH * G3;
            float* hdst = ((role == 0) ? g_h0s : g_h1s) + (size_t)(t + 1) * BH;
            float br = bhh[j], bz = bhh[HID + j], bnn = bhh[2 * HID + j];
            int joff = (j >> 7) * KSEG + (j & 127);
            #pragma unroll
            for (int bb = 0; bb < 2; bb++) {
                int i = 2 * ks + bb;
                int b = bg + 4 * i;
                float ghr = sv0[i] + br;
                float ghz = sv1[i] + bz;
                float ghn = sv2[i] + bnn;
                float gir = gi[(size_t)b * G3 + j];
                float giz = gi[(size_t)b * G3 + HID + j];
                float gin = gi[(size_t)b * G3 + 2 * HID + j];
                float r = 1.f / (1.f + expf(-(gir + ghr)));
                float z = 1.f / (1.f + expf(-(giz + ghz)));
                float n = tanhf(gin + r * ghn);
                float hprev = s_h[b * HPX + joff];
                float hnew = (1.f - z) * n + z * hprev;
                hdst[(size_t)b * HID + j] = hnew;
                if (role == 2) d_out[(size_t)t * BH + b * HID + j] = hnew;
                if (t == S - 1)
                    d_out[(size_t)S * BH + (role == 2 ? BH : 0) + b * HID + j] = hnew;
            }
        }

        __syncthreads();
        if (tid == 0) {
            int* f = (role == 0) ? &g_f0[t] : ((role == 1) ? &g_f1[t] : &g_f2[t]);
            red_release(f);
        }
    }
}

// ---------------- host launch ----------------
extern "C" void kernel_launch(void* const* d_in, const int* in_sizes, int n_in,
                              void* d_out, int out_size) {
    const float* x     = (const float*)d_in[0];
    const int*   ei    = (const int*)d_in[1];
    const float* W1    = (const float*)d_in[2];
    const float* b1    = (const float*)d_in[3];
    const float* W2    = (const float*)d_in[4];
    const float* b2    = (const float*)d_in[5];
    const float* w_ih0 = (const float*)d_in[6];
    const float* w_hh0 = (const float*)d_in[7];
    const float* b_ih0 = (const float*)d_in[8];
    const float* b_hh0 = (const float*)d_in[9];
    const float* w_ih1 = (const float*)d_in[10];
    const float* w_hh1 = (const float*)d_in[11];
    const float* b_ih1 = (const float*)d_in[12];
    const float* b_hh1 = (const float*)d_in[13];
    float* out = (float*)d_out;

    const int SMEM_GEMM = 2 * SAB;

    cudaFuncSetAttribute(gcn_kernel, cudaFuncAttributeMaxDynamicSharedMemorySize, SMEM_GCN);
    cudaFuncSetAttribute(gemm_gi0_kernel, cudaFuncAttributeMaxDynamicSharedMemorySize, SMEM_GEMM);
    cudaFuncSetAttribute(gru_persist_kernel, cudaFuncAttributeMaxDynamicSharedMemorySize, GRU_SMEM);

    init_kernel<<<(BH + 255) / 256, 256>>>(ei);
    count_kernel<<<(NEDGE + 255) / 256, 256>>>(ei);
    scan_kernel<<<1, 1024>>>();
    fill_kernel<<<(NEDGE_SL + 255) / 256, 256>>>(ei);

    gcn_kernel<<<GCN_CTAS + WCONV_CTAS, 1024, SMEM_GCN>>>(x, W1, b1, W2, b2, w_ih0);
    gemm_gi0_kernel<<<dim3(MP / 64, G3 / 64), 256, SMEM_GEMM>>>(b_ih0);

    gru_persist_kernel<<<96, 256, GRU_SMEM>>>(w_hh0, b_hh0, w_ih1, b_ih1,
                                              w_hh1, b_hh1, out);
}

// round 10
// speedup vs baseline: 3.2493x; 1.0017x over previous
#include <cuda_runtime.h>
#include <cuda_bf16.h>
#include <math.h>

#define S      15
#define BATCH  32
#define NNODE  5000
#define NEDGE  80000
#define NEDGE_SL (NEDGE + NNODE)
#define FIN    16
#define HID    512
#define G3     1536
#define SB     (S*BATCH)
#define K5     5000
#define K5P    5056
#define MP     512
#define KCH    158
#define BH     (BATCH*HID)
#define SLC    3
#define GCN_CTAS (SB / SLC)
#define WCONV_CTAS 40
#define P1_CTAS 313
#define P2_CTAS 84

typedef unsigned long long ull;

struct __align__(8) Edge { int s; float w; };

__device__ int   g_indeg[NNODE];
__device__ int   g_off[NNODE + 1];
__device__ int   g_pos[NNODE];
__device__ float g_dinv[NNODE];
__device__ Edge  g_edges[NEDGE_SL];
__device__ int   g_is64;
__device__ int   g_sync1;   // prep1 grid barrier (reset by prep2)
__device__ int   g_sync2;   // prep2 scan-done flag (reset by prep1)

__device__ __nv_bfloat16 g_ghi[MP * K5P];
__device__ __nv_bfloat16 g_glo[MP * K5P];
__device__ __nv_bfloat16 g_whi[G3 * K5P];
__device__ __nv_bfloat16 g_wlo[G3 * K5P];

__device__ float g_gi0[SB * G3];
__device__ float g_gi1[S * BATCH * G3];
__device__ float g_h0s[(S + 1) * BH];
__device__ float g_h1s[(S + 1) * BH];
__device__ int   g_f0[S], g_f1[S], g_f2[S];

#define FFMA2(c, a, b) asm("fma.rn.f32x2 %0, %1, %2, %0;" : "+l"(c) : "l"(a), "l"(b))
__device__ __forceinline__ float hsum2(ull v) {
    float lo, hi;
    asm("mov.b64 {%0,%1}, %2;" : "=f"(lo), "=f"(hi) : "l"(v));
    return lo + hi;
}
__device__ __forceinline__ unsigned smem_u32(const void* p) {
    return (unsigned)__cvta_generic_to_shared(p);
}
__device__ __forceinline__ void ldm_x4(unsigned a, unsigned& r0, unsigned& r1,
                                       unsigned& r2, unsigned& r3) {
    asm volatile("ldmatrix.sync.aligned.m8n8.x4.shared.b16 {%0,%1,%2,%3}, [%4];"
                 : "=r"(r0), "=r"(r1), "=r"(r2), "=r"(r3) : "r"(a));
}
__device__ __forceinline__ void mma_bf16(float* d, const unsigned* a, const unsigned* b) {
    asm volatile(
        "mma.sync.aligned.m16n8k16.row.col.f32.bf16.bf16.f32 "
        "{%0,%1,%2,%3}, {%4,%5,%6,%7}, {%8,%9}, {%0,%1,%2,%3};"
        : "+f"(d[0]), "+f"(d[1]), "+f"(d[2]), "+f"(d[3])
        : "r"(a[0]), "r"(a[1]), "r"(a[2]), "r"(a[3]), "r"(b[0]), "r"(b[1]));
}
__device__ __forceinline__ void spin_ge(const int* p, int n) {
    int v;
    do {
        asm volatile("ld.acquire.gpu.b32 %0, [%1];" : "=r"(v) : "l"(p));
        if (v < n) __nanosleep(64);
    } while (v < n);
}
__device__ __forceinline__ void spin32(const int* p) { spin_ge(p, 32); }
__device__ __forceinline__ void red_release(int* p) {
    asm volatile("red.release.gpu.global.add.s32 [%0], %1;" :: "l"(p), "r"(1) : "memory");
}

// ---------------- prep1: init + (grid barrier) + count ----------------
__global__ __launch_bounds__(256) void prep1_kernel(const int* __restrict__ ei) {
    int gid = blockIdx.x * 256 + threadIdx.x;
    if (gid == 0) {
        int f = 1;
        for (int q = 0; q < 64; q++) if (ei[2 * q + 1] != 0) { f = 0; break; }
        g_is64 = f;
        g_sync2 = 0;   // reset prep2's flag for this replay
    }
    if (gid < NNODE) g_indeg[gid] = 1;
    if (gid < BH) { g_h0s[gid] = 0.f; g_h1s[gid] = 0.f; }
    if (gid < S) { g_f0[gid] = 0; g_f1[gid] = 0; g_f2[gid] = 0; }
    __syncthreads();
    if (threadIdx.x == 0) {
        red_release(&g_sync1);          // release: init writes visible
        spin_ge(&g_sync1, P1_CTAS);     // grid barrier (all 313 CTAs resident)
    }
    __syncthreads();
    // count phase
    if (gid < NEDGE) {
        int t = g_is64 ? ei[2 * (NEDGE + gid)] : ei[NEDGE + gid];
        atomicAdd(&g_indeg[t], 1);
    }
}

// ---------------- prep2: scan (CTA0) + flag + fill (all CTAs) ----------------
__global__ __launch_bounds__(1024) void prep2_kernel(const int* __restrict__ ei) {
    int tid = threadIdx.x;
    if (blockIdx.x == 0) {
        __shared__ int ssum[1024];
        int vals[5]; int s = 0;
        #pragma unroll
        for (int q = 0; q < 5; q++) {
            int idx = tid * 5 + q;
            vals[q] = (idx < NNODE) ? g_indeg[idx] : 0;
            s += vals[q];
        }
        ssum[tid] = s;
        __syncthreads();
        for (int off = 1; off < 1024; off <<= 1) {
            int v = (tid >= off) ? ssum[tid - off] : 0;
            __syncthreads();
            ssum[tid] += v;
            __syncthreads();
        }
        int run = ssum[tid] - s;
        #pragma unroll
        for (int q = 0; q < 5; q++) {
            int idx = tid * 5 + q;
            if (idx < NNODE) {
                g_off[idx] = run; g_pos[idx] = run;
                g_dinv[idx] = rsqrtf((float)vals[q]);
                run += vals[q];
            }
        }
        if (tid == 1023) g_off[NNODE] = ssum[1023];
        __syncthreads();
        if (tid == 0) {
            g_sync1 = 0;                // reset prep1's barrier for next replay
            red_release(&g_sync2);
        }
    }
    if (tid == 0) spin_ge(&g_sync2, 1);
    __syncthreads();
    // fill phase
    int e = blockIdx.x * 1024 + tid;
    if (e >= NEDGE_SL) return;
    int is64 = g_is64;
    int s, t;
    if (e < NEDGE) {
        s = is64 ? ei[2 * e] : ei[e];
        t = is64 ? ei[2 * (NEDGE + e)] : ei[NEDGE + e];
    } else { s = t = e - NEDGE; }
    int idx = atomicAdd(&g_pos[t], 1);
    Edge E; E.s = s; E.w = g_dinv[s] * g_dinv[t];
    g_edges[idx] = E;
}

// ---------------- fused GCN + wconv (unchanged R9 winner) ----------------
#define SMEM_GCN ((NNODE * 6 + NNODE * 3) * 4)

__global__ __launch_bounds__(1024) void gcn_kernel(const float* __restrict__ x,
                                                   const float* __restrict__ W1,
                                                   const float* __restrict__ b1,
                                                   const float* __restrict__ W2,
                                                   const float* __restrict__ b2,
                                                   const float* __restrict__ wih0) {
    int cta = blockIdx.x, tid = threadIdx.x;

    if (cta >= GCN_CTAS) {
        int base = (cta - GCN_CTAS) * 1024 + tid;
        for (int i = base; i < G3 * K5; i += WCONV_CTAS * 1024) {
            int n = i / K5, k = i - n * K5;
            float v = wih0[i];
            __nv_bfloat16 hi = __float2bfloat16(v);
            g_whi[(size_t)n * K5P + k] = hi;
            g_wlo[(size_t)n * K5P + k] = __float2bfloat16(v - __bfloat162float(hi));
        }
        return;
    }

    extern __shared__ float sm[];
    float* hA = sm;
    float* h2 = sm + NNODE * 6;
    __shared__ float s_w1[SLC][FIN][2];
    __shared__ float s_b1[SLC][2], s_w2[SLC][2], s_b2[SLC];

    if (tid < SLC * FIN * 2) {
        int sl = tid / (FIN * 2), rem = tid % (FIN * 2);
        int s = (cta * SLC + sl) >> 5;
        s_w1[sl][rem >> 1][rem & 1] = W1[s * (FIN * 2) + rem];
    }
    if (tid >= 128 && tid < 128 + SLC * 2) {
        int q = tid - 128; int sl = q >> 1, c = q & 1;
        int s = (cta * SLC + sl) >> 5;
        s_b1[sl][c] = b1[s * 2 + c];
        s_w2[sl][c] = W2[s * 2 + c];
    }
    if (tid >= 160 && tid < 160 + SLC) {
        int sl = tid - 160;
        s_b2[sl] = b2[((cta * SLC + sl) >> 5)];
    }
    __syncthreads();

    for (int idx = tid; idx < SLC * NNODE; idx += 1024) {
        int sl = idx / NNODE, n = idx - sl * NNODE;
        const float4* xp = (const float4*)(x + ((size_t)(cta * SLC + sl) * NNODE + n) * FIN);
        float xv[16];
        *(float4*)&xv[0] = xp[0]; *(float4*)&xv[4] = xp[1];
        *(float4*)&xv[8] = xp[2]; *(float4*)&xv[12] = xp[3];
        float a0 = 0.f, a1 = 0.f;
        #pragma unroll
        for (int f = 0; f < FIN; f++) {
            a0 += xv[f] * s_w1[sl][f][0];
            a1 += xv[f] * s_w1[sl][f][1];
        }
        hA[n * 6 + sl * 2]     = a0;
        hA[n * 6 + sl * 2 + 1] = a1;
    }
    __syncthreads();

    int warp = tid >> 5, lane = tid & 31;
    int seg = lane >> 3, sub = lane & 7;

    for (int n0 = warp * 4; n0 < NNODE; n0 += 128) {
        int n = n0 + seg;
        int e0 = g_off[n], e1 = g_off[n + 1];
        float ac0 = 0.f, ac1 = 0.f, ac2 = 0.f, ac3 = 0.f, ac4 = 0.f, ac5 = 0.f;
        for (int e = e0 + sub; e < e1; e += 8) {
            Edge E = g_edges[e];
            const float2* src = (const float2*)(hA + E.s * 6);
            float2 p0 = src[0], p1 = src[1], p2 = src[2];
            ac0 += E.w * p0.x; ac1 += E.w * p0.y;
            ac2 += E.w * p1.x; ac3 += E.w * p1.y;
            ac4 += E.w * p2.x; ac5 += E.w * p2.y;
        }
        #pragma unroll
        for (int m = 4; m >= 1; m >>= 1) {
            ac0 += __shfl_xor_sync(0xFFFFFFFF, ac0, m);
            ac1 += __shfl_xor_sync(0xFFFFFFFF, ac1, m);
            ac2 += __shfl_xor_sync(0xFFFFFFFF, ac2, m);
            ac3 += __shfl_xor_sync(0xFFFFFFFF, ac3, m);
            ac4 += __shfl_xor_sync(0xFFFFFFFF, ac4, m);
            ac5 += __shfl_xor_sync(0xFFFFFFFF, ac5, m);
        }
        if (sub == 0) {
            float r0, r1;
            r0 = fmaxf(ac0 + s_b1[0][0], 0.f); r1 = fmaxf(ac1 + s_b1[0][1], 0.f);
            h2[n * 3 + 0] = r0 * s_w2[0][0] + r1 * s_w2[0][1];
            r0 = fmaxf(ac2 + s_b1[1][0], 0.f); r1 = fmaxf(ac3 + s_b1[1][1], 0.f);
            h2[n * 3 + 1] = r0 * s_w2[1][0] + r1 * s_w2[1][1];
            r0 = fmaxf(ac4 + s_b1[2][0], 0.f); r1 = fmaxf(ac5 + s_b1[2][1], 0.f);
            h2[n * 3 + 2] = r0 * s_w2[2][0] + r1 * s_w2[2][1];
        }
    }
    __syncthreads();

    for (int n0 = warp * 4; n0 < NNODE; n0 += 128) {
        int n = n0 + seg;
        int e0 = g_off[n], e1 = g_off[n + 1];
        float a0 = 0.f, a1 = 0.f, a2 = 0.f;
        for (int e = e0 + sub; e < e1; e += 8) {
            Edge E = g_edges[e];
            const float* src = h2 + E.s * 3;
            a0 += E.w * src[0];
            a1 += E.w * src[1];
            a2 += E.w * src[2];
        }
        #pragma unroll
        for (int m = 4; m >= 1; m >>= 1) {
            a0 += __shfl_xor_sync(0xFFFFFFFF, a0, m);
            a1 += __shfl_xor_sync(0xFFFFFFFF, a1, m);
            a2 += __shfl_xor_sync(0xFFFFFFFF, a2, m);
        }
        if (sub == 0) {
            hA[n * 3 + 0] = a0;
            hA[n * 3 + 1] = a1;
            hA[n * 3 + 2] = a2;
        }
    }
    __syncthreads();

    for (int n = tid; n < NNODE; n += 1024) {
        #pragma unroll
        for (int sl = 0; sl < SLC; sl++) {
            float g = tanhf(hA[n * 3 + sl] + s_b2[sl]);
            int sb = cta * SLC + sl;
            __nv_bfloat16 hi = __float2bfloat16(g);
            g_ghi[(size_t)sb * K5P + n] = hi;
            g_glo[(size_t)sb * K5P + n] = __float2bfloat16(g - __bfloat162float(hi));
        }
    }
}

// ---------------- gi0 GEMM (unchanged R8 winner) ----------------
#define GSTR 72
#define SAB  36864

__global__ __launch_bounds__(256, 2) void gemm_gi0_kernel(const float* __restrict__ bih0) {
    extern __shared__ char smraw[];
    __nv_bfloat16* sA = (__nv_bfloat16*)smraw;
    __nv_bfloat16* sB = (__nv_bfloat16*)(smraw + SAB);
    unsigned sA_u = smem_u32(sA), sB_u = smem_u32(sB);

    int tid = threadIdx.x;
    int lane = tid & 31, warp = tid >> 5;
    int wm = warp >> 2, wn = warp & 3;
    int m0 = blockIdx.x * 64, n0 = blockIdx.y * 64;

    float d[2][2][4];
    #pragma unroll
    for (int i = 0; i < 2; i++)
        #pragma unroll
        for (int j = 0; j < 2; j++)
            #pragma unroll
            for (int q = 0; q < 4; q++) d[i][j][q] = 0.f;

    int hl_[2], row_[2], seg_[2];
    #pragma unroll
    for (int i = 0; i < 2; i++) {
        int idx = tid + i * 256;
        hl_[i] = idx >> 8; int r = idx & 255;
        row_[i] = r >> 2; seg_[i] = r & 3;
    }

    uint4 rA[2], rB[2];
    #pragma unroll
    for (int i = 0; i < 2; i++) {
        const __nv_bfloat16* sa = hl_[i] ? g_glo : g_ghi;
        const __nv_bfloat16* sb = hl_[i] ? g_wlo : g_whi;
        rA[i] = *(const uint4*)(sa + (size_t)(m0 + row_[i]) * K5P + seg_[i] * 8);
        rB[i] = *(const uint4*)(sb + (size_t)(n0 + row_[i]) * K5P + seg_[i] * 8);
    }
    #pragma unroll
    for (int i = 0; i < 2; i++) {
        *(uint4*)(sA + ((hl_[i]) * 64 + row_[i]) * GSTR + seg_[i] * 8) = rA[i];
        *(uint4*)(sB + ((hl_[i]) * 64 + row_[i]) * GSTR + seg_[i] * 8) = rB[i];
    }
    __syncthreads();

    for (int c = 0; c < KCH; c++) {
        int buf = c & 1;
        if (c + 1 < KCH) {
            int kb = (c + 1) * 32;
            #pragma unroll
            for (int i = 0; i < 2; i++) {
                const __nv_bfloat16* sa = hl_[i] ? g_glo : g_ghi;
                const __nv_bfloat16* sb = hl_[i] ? g_wlo : g_whi;
                rA[i] = *(const uint4*)(sa + (size_t)(m0 + row_[i]) * K5P + kb + seg_[i] * 8);
                rB[i] = *(const uint4*)(sb + (size_t)(n0 + row_[i]) * K5P + kb + seg_[i] * 8);
            }
        }
        #pragma unroll
        for (int kk = 0; kk < 2; kk++) {
            unsigned a[2][2][4], bf[2][2][2];
            int arow = lane & 15;
            int acol = kk * 16 + ((lane >> 4) << 3);
            #pragma unroll
            for (int hl = 0; hl < 2; hl++)
                #pragma unroll
                for (int mi = 0; mi < 2; mi++) {
                    unsigned ad = sA_u +
                        (((buf * 2 + hl) * 64 + wm * 32 + mi * 16 + arow) * GSTR + acol) * 2;
                    ldm_x4(ad, a[hl][mi][0], a[hl][mi][1], a[hl][mi][2], a[hl][mi][3]);
                }
            int bn = (lane & 7) + ((lane >> 4) & 1) * 8;
            int bk = kk * 16 + (lane & 8);
            #pragma unroll
            for (int hl = 0; hl < 2; hl++) {
                unsigned r0, r1, r2, r3;
                unsigned ad = sB_u +
                    (((buf * 2 + hl) * 64 + wn * 16 + bn) * GSTR + bk) * 2;
                ldm_x4(ad, r0, r1, r2, r3);
                bf[hl][0][0] = r0; bf[hl][0][1] = r1;
                bf[hl][1][0] = r2; bf[hl][1][1] = r3;
            }
            #pragma unroll
            for (int mi = 0; mi < 2; mi++)
                #pragma unroll
                for (int j = 0; j < 2; j++) {
                    mma_bf16(d[mi][j], a[0][mi], bf[0][j]);
                    mma_bf16(d[mi][j], a[0][mi], bf[1][j]);
                    mma_bf16(d[mi][j], a[1][mi], bf[0][j]);
                }
        }
        if (c + 1 < KCH) {
            int nb = buf ^ 1;
            #pragma unroll
            for (int i = 0; i < 2; i++) {
                *(uint4*)(sA + ((nb * 2 + hl_[i]) * 64 + row_[i]) * GSTR + seg_[i] * 8) = rA[i];
                *(uint4*)(sB + ((nb * 2 + hl_[i]) * 64 + row_[i]) * GSTR + seg_[i] * 8) = rB[i];
            }
        }
        __syncthreads();
    }

    #pragma unroll
    for (int mi = 0; mi < 2; mi++)
        #pragma unroll
        for (int j = 0; j < 2; j++) {
            int row0 = m0 + wm * 32 + mi * 16 + (lane >> 2);
            int col = n0 + wn * 16 + j * 8 + (lane & 3) * 2;
            float bia = bih0[col], bib = bih0[col + 1];
            if (row0 < SB) {
                g_gi0[(size_t)row0 * G3 + col]     = d[mi][j][0] + bia;
                g_gi0[(size_t)row0 * G3 + col + 1] = d[mi][j][1] + bib;
            }
            if (row0 + 8 < SB) {
                g_gi0[(size_t)(row0 + 8) * G3 + col]     = d[mi][j][2] + bia;
                g_gi0[(size_t)(row0 + 8) * G3 + col + 1] = d[mi][j][3] + bib;
            }
        }
}

// ---------------- persistent GRU (unchanged R9 winner) ----------------
#define KSEG 136
#define HPX  546
#define WPS  548
#define GRU_SMEM ((48 * WPS + 32 * HPX) * 4)

__global__ __launch_bounds__(256, 1) void gru_persist_kernel(
        const float* __restrict__ whh0, const float* __restrict__ bhh0,
        const float* __restrict__ wih1, const float* __restrict__ bih1,
        const float* __restrict__ whh1, const float* __restrict__ bhh1,
        float* __restrict__ d_out) {
    extern __shared__ float sm[];
    float* s_w = sm;
    float* s_h = sm + 48 * WPS;
    int tid = threadIdx.x;
    int role = blockIdx.x >> 5;
    int c = blockIdx.x & 31;

    const float* wsrc = (role == 0) ? whh0 : ((role == 1) ? wih1 : whh1);
    for (int e = tid; e < 48 * 512; e += 256) {
        int r = e >> 9, k = e & 511;
        int G = (role == 1) ? (c * 48 + r) : ((r >> 4) * HID + c * 16 + (r & 15));
        s_w[r * WPS + (k >> 7) * KSEG + (k & 127)] = wsrc[(size_t)G * HID + k];
    }

    int jl = tid >> 4, r4 = tid & 15, ks = r4 >> 2, bg = r4 & 3;
    const ull* wp0 = (const ull*)(s_w + (0 * 16 + jl) * WPS + ks * KSEG);
    const ull* wp1 = (const ull*)(s_w + (1 * 16 + jl) * WPS + ks * KSEG);
    const ull* wp2 = (const ull*)(s_w + (2 * 16 + jl) * WPS + ks * KSEG);
    const ull* hp[8];
    #pragma unroll
    for (int i = 0; i < 8; i++)
        hp[i] = (const ull*)(s_h + (bg + 4 * i) * HPX + ks * KSEG);

    for (int t = 0; t < S; t++) {
        if (tid == 0) {
            if (role == 0) { if (t) spin32(&g_f0[t - 1]); }
            else if (role == 1) { spin32(&g_f0[t]); }
            else { spin32(&g_f1[t]); if (t) spin32(&g_f2[t - 1]); }
        }
        __syncthreads();

        const float* hsrc = (role == 0) ? (g_h0s + (size_t)t * BH)
                          : (role == 1) ? (g_h0s + (size_t)(t + 1) * BH)
                                        : (g_h1s + (size_t)t * BH);
        for (int e = tid; e < 32 * 128; e += 256) {
            int b = e >> 7, k4 = (e & 127) * 4;
            float4 v = *(const float4*)(hsrc + (size_t)b * HID + k4);
            float* dst = s_h + b * HPX + (k4 >> 7) * KSEG + (k4 & 127);
            *(float2*)dst = make_float2(v.x, v.y);
            *(float2*)(dst + 2) = make_float2(v.z, v.w);
        }
        __syncthreads();

        ull a0[8], a1[8], a2[8];
        #pragma unroll
        for (int i = 0; i < 8; i++) { a0[i] = 0ull; a1[i] = 0ull; a2[i] = 0ull; }

        #pragma unroll 2
        for (int q = 0; q < 64; q++) {
            ull v0 = wp0[q], v1 = wp1[q], v2 = wp2[q];
            #pragma unroll
            for (int i = 0; i < 8; i++) {
                ull h = hp[i][q];
                FFMA2(a0[i], h, v0);
                FFMA2(a1[i], h, v1);
                FFMA2(a2[i], h, v2);
            }
        }

        float sv0[8], sv1[8], sv2[8];
        #pragma unroll
        for (int i = 0; i < 8; i++) {
            float v;
            v = hsum2(a0[i]);
            v += __shfl_xor_sync(0xFFFFFFFF, v, 4);
            v += __shfl_xor_sync(0xFFFFFFFF, v, 8);
            sv0[i] = v;
            v = hsum2(a1[i]);
            v += __shfl_xor_sync(0xFFFFFFFF, v, 4);
            v += __shfl_xor_sync(0xFFFFFFFF, v, 8);
            sv1[i] = v;
            v = hsum2(a2[i]);
            v += __shfl_xor_sync(0xFFFFFFFF, v, 4);
            v += __shfl_xor_sync(0xFFFFFFFF, v, 8);
            sv2[i] = v;
        }

        if (role == 1) {
            float* gi = g_gi1 + (size_t)t * BATCH * G3;
            int r0 = c * 48 + jl, r1 = r0 + 16, r2 = r0 + 32;
            float b0 = bih1[r0], b1v = bih1[r1], b2v = bih1[r2];
            #pragma unroll
            for (int bb = 0; bb < 2; bb++) {
                int i = 2 * ks + bb;
                int b = bg + 4 * i;
                gi[(size_t)b * G3 + r0] = sv0[i] + b0;
                gi[(size_t)b * G3 + r1] = sv1[i] + b1v;
                gi[(size_t)b * G3 + r2] = sv2[i] + b2v;
            }
        } else {
            int j = c * 16 + jl;
            const float* bhh = (role == 0) ? bhh0 : bhh1;
            const float* gi = ((role == 0) ? g_gi0 : g_gi1) + (size_t)t * BATCH * G3;
            float* hdst = ((role == 0) ? g_h0s : g_h1s) + (size_t)(t + 1) * BH;
            float br = bhh[j], bz = bhh[HID + j], bnn = bhh[2 * HID + j];
            int joff = (j >> 7) * KSEG + (j & 127);
            #pragma unroll
            for (int bb = 0; bb < 2; bb++) {
                int i = 2 * ks + bb;
                int b = bg + 4 * i;
                float ghr = sv0[i] + br;
                float ghz = sv1[i] + bz;
                float ghn = sv2[i] + bnn;
                float gir = gi[(size_t)b * G3 + j];
                float giz = gi[(size_t)b * G3 + HID + j];
                float gin = gi[(size_t)b * G3 + 2 * HID + j];
                float r = 1.f / (1.f + expf(-(gir + ghr)));
                float z = 1.f / (1.f + expf(-(giz + ghz)));
                float n = tanhf(gin + r * ghn);
                float hprev = s_h[b * HPX + joff];
                float hnew = (1.f - z) * n + z * hprev;
                hdst[(size_t)b * HID + j] = hnew;
                if (role == 2) d_out[(size_t)t * BH + b * HID + j] = hnew;
                if (t == S - 1)
                    d_out[(size_t)S * BH + (role == 2 ? BH : 0) + b * HID + j] = hnew;
            }
        }

        __syncthreads();
        if (tid == 0) {
            int* f = (role == 0) ? &g_f0[t] : ((role == 1) ? &g_f1[t] : &g_f2[t]);
            red_release(f);
        }
    }
}

// ---------------- host launch ----------------
extern "C" void kernel_launch(void* const* d_in, const int* in_sizes, int n_in,
                              void* d_out, int out_size) {
    const float* x     = (const float*)d_in[0];
    const int*   ei    = (const int*)d_in[1];
    const float* W1    = (const float*)d_in[2];
    const float* b1    = (const float*)d_in[3];
    const float* W2    = (const float*)d_in[4];
    const float* b2    = (const float*)d_in[5];
    const float* w_ih0 = (const float*)d_in[6];
    const float* w_hh0 = (const float*)d_in[7];
    const float* b_ih0 = (const float*)d_in[8];
    const float* b_hh0 = (const float*)d_in[9];
    const float* w_ih1 = (const float*)d_in[10];
    const float* w_hh1 = (const float*)d_in[11];
    const float* b_ih1 = (const float*)d_in[12];
    const float* b_hh1 = (const float*)d_in[13];
    float* out = (float*)d_out;

    const int SMEM_GEMM = 2 * SAB;

    cudaFuncSetAttribute(gcn_kernel, cudaFuncAttributeMaxDynamicSharedMemorySize, SMEM_GCN);
    cudaFuncSetAttribute(gemm_gi0_kernel, cudaFuncAttributeMaxDynamicSharedMemorySize, SMEM_GEMM);
    cudaFuncSetAttribute(gru_persist_kernel, cudaFuncAttributeMaxDynamicSharedMemorySize, GRU_SMEM);

    prep1_kernel<<<P1_CTAS, 256>>>(ei);
    prep2_kernel<<<P2_CTAS, 1024>>>(ei);
    gcn_kernel<<<GCN_CTAS + WCONV_CTAS, 1024, SMEM_GCN>>>(x, W1, b1, W2, b2, w_ih0);
    gemm_gi0_kernel<<<dim3(MP / 64, G3 / 64), 256, SMEM_GEMM>>>(b_ih0);   // capture slot #4
    gru_persist_kernel<<<96, 256, GRU_SMEM>>>(w_hh0, b_hh0, w_ih1, b_ih1,
                                              w_hh1, b_hh1, out);
}